// round 1
// baseline (speedup 1.0000x reference)
#include <cuda_runtime.h>
#include <math.h>

#define NSENS 9
#define NEDGE 72
#define NPAIR 36
#define HDIM  128
#define NLAY  4
#define NTHREADS 256
#define EPSF 1e-8f

// ---------------------------------------------------------------------------
// Shared-memory working set for one graph (one CTA per graph).
// ---------------------------------------------------------------------------
struct SM {
    float h_n[NSENS][HDIM];    // node features
    float h_e[NEDGE][HDIM];    // edge features
    float hid[NEDGE][HDIM];    // MLP hidden scratch (reused by node MLP + decoder)
    float agg[NSENS][HDIM];    // mean-aggregated sender features
    float phys[NEDGE][8];      // 6 physical edge features (padded to 8)
    float xs[NSENS][2];
    float dmg[2];
    float deg[NSENS];
    float dec[NEDGE];
    int   row_l[NEDGE];
    int   col_l[NEDGE];
    int   senders[NSENS][8];
    int   scnt[NSENS];
};

// ---------------------------------------------------------------------------
// Packed f32x2 helpers (sm_103a: FFMA 3-reg runs at half rate; f32x2 is full)
// ---------------------------------------------------------------------------
__device__ __forceinline__ unsigned long long pack2(float x) {
    unsigned long long r;
    asm("mov.b64 %0, {%1, %1};" : "=l"(r) : "f"(x));
    return r;
}
__device__ __forceinline__ void ffma2(unsigned long long& d,
                                      unsigned long long a,
                                      unsigned long long b) {
    asm("fma.rn.f32x2 %0, %1, %2, %0;" : "+l"(d) : "l"(a), "l"(b));
}
__device__ __forceinline__ float2 unpack2(unsigned long long v) {
    float lo, hi;
    asm("mov.b64 {%0, %1}, %2;" : "=f"(lo), "=f"(hi) : "l"(v));
    return make_float2(lo, hi);
}

// ---------------------------------------------------------------------------
// Register-tiled [72 x 128] = A[72 x 128] @ W[128 x 128] (+bias, epilogue).
// Thread layout: warp eg (0..7) owns edges eg*9..eg*9+8; lane hg owns cols 4*hg..+3.
// EPI: 0 -> OUT = relu(acc + bias); 1 -> OUT += acc + bias; 2 -> OUT = acc + bias
// ---------------------------------------------------------------------------
template <int EPI>
__device__ __forceinline__ void tile_gemm128(
    const float* __restrict__ W, const float* __restrict__ bias,
    const float (*__restrict__ A)[HDIM], float (*__restrict__ OUT)[HDIM],
    int eg, int hg)
{
    unsigned long long acc[9][2];
#pragma unroll
    for (int m = 0; m < 9; ++m) { acc[m][0] = 0ull; acc[m][1] = 0ull; }

    const float* ab[9];
#pragma unroll
    for (int m = 0; m < 9; ++m) ab[m] = A[eg * 9 + m];

    const float* wp = W + (hg << 2);
#pragma unroll 4
    for (int k = 0; k < HDIM; ++k) {
        ulonglong2 bv = *(const ulonglong2*)(wp + k * HDIM);
#pragma unroll
        for (int m = 0; m < 9; ++m) {
            unsigned long long a2 = pack2(ab[m][k]);
            ffma2(acc[m][0], a2, bv.x);
            ffma2(acc[m][1], a2, bv.y);
        }
    }

    float4 bb = *(const float4*)(bias + (hg << 2));
#pragma unroll
    for (int m = 0; m < 9; ++m) {
        int e = eg * 9 + m;
        float2 v0 = unpack2(acc[m][0]);
        float2 v1 = unpack2(acc[m][1]);
        float4* o = (float4*)&OUT[e][hg << 2];
        float4 r;
        if (EPI == 0) {
            r = make_float4(fmaxf(v0.x + bb.x, 0.f), fmaxf(v0.y + bb.y, 0.f),
                            fmaxf(v1.x + bb.z, 0.f), fmaxf(v1.y + bb.w, 0.f));
        } else if (EPI == 1) {
            float4 p = *o;
            r = make_float4(p.x + v0.x + bb.x, p.y + v0.y + bb.y,
                            p.z + v1.x + bb.z, p.w + v1.y + bb.w);
        } else {
            r = make_float4(v0.x + bb.x, v0.y + bb.y, v1.x + bb.z, v1.y + bb.w);
        }
        *o = r;
    }
}

// K=384 GEMM for the edge update: ein = [h_n[row], h_n[col], h_e] per edge,
// never materialized -- 3 K-segments with per-segment A-row base pointers.
__device__ __forceinline__ void edge_gemm1(
    const float* __restrict__ W, const float* __restrict__ bias,
    SM& sm, int eg, int hg)
{
    unsigned long long acc[9][2];
#pragma unroll
    for (int m = 0; m < 9; ++m) { acc[m][0] = 0ull; acc[m][1] = 0ull; }

#pragma unroll 1
    for (int s = 0; s < 3; ++s) {
        const float* ab[9];
#pragma unroll
        for (int m = 0; m < 9; ++m) {
            int e = eg * 9 + m;
            ab[m] = (s == 0) ? sm.h_n[sm.row_l[e]]
                  : (s == 1) ? sm.h_n[sm.col_l[e]]
                             : sm.h_e[e];
        }
        const float* wp = W + s * HDIM * HDIM + (hg << 2);
#pragma unroll 4
        for (int k = 0; k < HDIM; ++k) {
            ulonglong2 bv = *(const ulonglong2*)(wp + k * HDIM);
#pragma unroll
            for (int m = 0; m < 9; ++m) {
                unsigned long long a2 = pack2(ab[m][k]);
                ffma2(acc[m][0], a2, bv.x);
                ffma2(acc[m][1], a2, bv.y);
            }
        }
    }

    float4 bb = *(const float4*)(bias + (hg << 2));
#pragma unroll
    for (int m = 0; m < 9; ++m) {
        int e = eg * 9 + m;
        float2 v0 = unpack2(acc[m][0]);
        float2 v1 = unpack2(acc[m][1]);
        *(float4*)&sm.hid[e][hg << 2] =
            make_float4(fmaxf(v0.x + bb.x, 0.f), fmaxf(v0.y + bb.y, 0.f),
                        fmaxf(v1.x + bb.z, 0.f), fmaxf(v1.y + bb.w, 0.f));
    }
}

// ---------------------------------------------------------------------------
// Fused GNN kernel: one CTA per graph, 256 threads.
// ---------------------------------------------------------------------------
__global__ __launch_bounds__(NTHREADS, 2)
void DirectPathAttenuationGNN_kernel(
    const float* __restrict__ x_nodes, const float* __restrict__ damage,
    const float* __restrict__ enc_n_w, const float* __restrict__ enc_n_b,
    const float* __restrict__ enc_e_w1, const float* __restrict__ enc_e_b1,
    const float* __restrict__ enc_e_w2, const float* __restrict__ enc_e_b2,
    const float* __restrict__ edge_w1, const float* __restrict__ edge_b1,
    const float* __restrict__ edge_w2, const float* __restrict__ edge_b2,
    const float* __restrict__ node_w1, const float* __restrict__ node_b1,
    const float* __restrict__ node_w2, const float* __restrict__ node_b2,
    const float* __restrict__ dec_w1, const float* __restrict__ dec_b1,
    const float* __restrict__ dec_w2, const float* __restrict__ dec_b2,
    const int* __restrict__ edge_index, int Etot,
    float* __restrict__ out)
{
    extern __shared__ unsigned char smem_raw[];
    SM& sm = *reinterpret_cast<SM*>(smem_raw);

    const int g   = blockIdx.x;
    const int tid = threadIdx.x;
    const int eg  = tid >> 5;   // warp id: edge group
    const int hg  = tid & 31;   // lane: column group (4 cols)

    // ---- load per-graph inputs -------------------------------------------
    if (tid < NEDGE) {
        int ge = g * NEDGE + tid;
        sm.row_l[tid] = edge_index[ge]        - g * NSENS;
        sm.col_l[tid] = edge_index[Etot + ge] - g * NSENS;
    }
    if (tid < NSENS * 2) ((float*)sm.xs)[tid] = x_nodes[g * NSENS * 2 + tid];
    if (tid < 2)         sm.dmg[tid] = damage[g * 2 + tid];
    __syncthreads();

    // ---- sender lists + degree (generic, from actual edge_index) ---------
    if (tid < NSENS) {
        int cnt = 0;
        for (int e = 0; e < NEDGE; ++e)
            if (sm.col_l[e] == tid) { if (cnt < 8) sm.senders[tid][cnt] = sm.row_l[e]; ++cnt; }
        sm.scnt[tid] = cnt < 8 ? cnt : 8;
        sm.deg[tid]  = fmaxf((float)cnt, 1.0f);
    }

    // ---- physical edge features ------------------------------------------
    if (tid < NEDGE) {
        int r = sm.row_l[tid], c = sm.col_l[tid];
        float sx = sm.xs[r][0], sy = sm.xs[r][1];
        float dx = sm.xs[c][0], dy = sm.xs[c][1];
        float g0 = sm.dmg[0],   g1 = sm.dmg[1];
        float vx = sx - dx, vy = sy - dy;
        float elen = sqrtf(vx * vx + vy * vy + EPSF);
        float d21x = -vx, d21y = -vy;
        float l2 = fmaxf(d21x * d21x + d21y * d21y, EPSF);
        float mx = g0 - sx, my = g1 - sy;
        float t = fminf(fmaxf((mx * d21x + my * d21y) / l2, 0.f), 1.f);
        float px = sx + t * d21x, py = sy + t * d21y;
        float qx = g0 - px, qy = g1 - py;
        float d_path = sqrtf(qx * qx + qy * qy + EPSF);
        float d_tx = sqrtf(mx * mx + my * my + EPSF);
        float rx = dx - g0, ry = dy - g1;
        float d_rx = sqrtf(rx * rx + ry * ry + EPSF);
        sm.phys[tid][0] = vx;   sm.phys[tid][1] = vy;
        sm.phys[tid][2] = elen; sm.phys[tid][3] = d_path;
        sm.phys[tid][4] = d_tx; sm.phys[tid][5] = d_rx;
    }

    // ---- node encoder: h_n = x @ Wn + bn (K=2) ----------------------------
    for (int idx = tid; idx < NSENS * HDIM; idx += NTHREADS) {
        int n = idx >> 7, h = idx & 127;
        sm.h_n[n][h] = sm.xs[n][0] * enc_n_w[h] + sm.xs[n][1] * enc_n_w[HDIM + h]
                     + enc_n_b[h];
    }
    __syncthreads();

    // ---- edge encoder hidden (K=6) -> hid ---------------------------------
    for (int idx = tid; idx < NEDGE * HDIM; idx += NTHREADS) {
        int e = idx >> 7, h = idx & 127;
        float a = enc_e_b1[h];
#pragma unroll
        for (int k = 0; k < 6; ++k) a += sm.phys[e][k] * enc_e_w1[k * HDIM + h];
        sm.hid[e][h] = fmaxf(a, 0.f);
    }
    __syncthreads();

    // ---- edge encoder out: h_e = hid @ W2 + b2 ----------------------------
    tile_gemm128<2>(enc_e_w2, enc_e_b2, sm.hid, sm.h_e, eg, hg);
    __syncthreads();

    // ---- 4 message-passing layers -----------------------------------------
    for (int l = 0; l < NLAY; ++l) {
        const float* w1 = edge_w1 + l * 3 * HDIM * HDIM;
        const float* b1 = edge_b1 + l * HDIM;
        const float* w2 = edge_w2 + l * HDIM * HDIM;
        const float* b2 = edge_b2 + l * HDIM;

        // edge MLP: hid = relu([h_n[row],h_n[col],h_e] @ w1 + b1)
        edge_gemm1(w1, b1, sm, eg, hg);
        __syncwarp();                       // hid rows are warp-private
        // h_e += hid @ w2 + b2
        tile_gemm128<1>(w2, b2, sm.hid, sm.h_e, eg, hg);
        __syncthreads();

        // mean aggregation of sender features at each receiver
        for (int idx = tid; idx < NSENS * HDIM; idx += NTHREADS) {
            int n = idx >> 7, h = idx & 127;
            float s = 0.f;
            int c = sm.scnt[n];
            for (int i = 0; i < c; ++i) s += sm.h_n[sm.senders[n][i]][h];
            sm.agg[n][h] = s / sm.deg[n];
        }
        __syncthreads();

        // node MLP hidden (K=256) -> reuse hid rows 0..8
        const float* nw1 = node_w1 + l * 2 * HDIM * HDIM;
        const float* nb1 = node_b1 + l * HDIM;
        for (int idx = tid; idx < NSENS * HDIM; idx += NTHREADS) {
            int n = idx >> 7, h = idx & 127;
            float a = nb1[h];
            const float* w = nw1 + h;
#pragma unroll 4
            for (int k = 0; k < HDIM; ++k) a += sm.h_n[n][k] * w[k * HDIM];
#pragma unroll 4
            for (int k = 0; k < HDIM; ++k) a += sm.agg[n][k] * w[(HDIM + k) * HDIM];
            sm.hid[n][h] = fmaxf(a, 0.f);
        }
        __syncthreads();

        // h_n += hid @ nw2 + nb2
        const float* nw2 = node_w2 + l * HDIM * HDIM;
        const float* nb2 = node_b2 + l * HDIM;
        for (int idx = tid; idx < NSENS * HDIM; idx += NTHREADS) {
            int n = idx >> 7, h = idx & 127;
            float a = nb2[h];
            const float* w = nw2 + h;
#pragma unroll 4
            for (int k = 0; k < HDIM; ++k) a += sm.hid[n][k] * w[k * HDIM];
            sm.h_n[n][h] += a;
        }
        __syncthreads();
    }

    // ---- decoder -----------------------------------------------------------
    float (*dhid)[64] = (float(*)[64])sm.hid;
    for (int idx = tid; idx < NEDGE * 64; idx += NTHREADS) {
        int e = idx >> 6, h = idx & 63;
        float a = dec_b1[h];
        const float* w = dec_w1 + h;
#pragma unroll 4
        for (int k = 0; k < HDIM; ++k) a += sm.h_e[e][k] * w[k * 64];
        dhid[e][h] = fmaxf(a, 0.f);
    }
    __syncthreads();
    if (tid < NEDGE) {
        float a = dec_b2[0];
#pragma unroll 4
        for (int k = 0; k < 64; ++k) a += dhid[tid][k] * dec_w2[k];
        sm.dec[tid] = 1.f / (1.f + expf(-a));
    }
    __syncthreads();
    if (tid < NPAIR)
        out[g * NPAIR + tid] = 0.5f * (sm.dec[2 * tid] + sm.dec[2 * tid + 1]);
}

// ---------------------------------------------------------------------------
// Harness entry point
// ---------------------------------------------------------------------------
extern "C" void kernel_launch(void* const* d_in, const int* in_sizes, int n_in,
                              void* d_out, int out_size)
{
    const float* x_nodes   = (const float*)d_in[0];
    const float* damage    = (const float*)d_in[1];
    const float* enc_n_w   = (const float*)d_in[2];
    const float* enc_n_b   = (const float*)d_in[3];
    const float* enc_e_w1  = (const float*)d_in[4];
    const float* enc_e_b1  = (const float*)d_in[5];
    const float* enc_e_w2  = (const float*)d_in[6];
    const float* enc_e_b2  = (const float*)d_in[7];
    const float* edge_w1   = (const float*)d_in[8];
    const float* edge_b1   = (const float*)d_in[9];
    const float* edge_w2   = (const float*)d_in[10];
    const float* edge_b2   = (const float*)d_in[11];
    const float* node_w1   = (const float*)d_in[12];
    const float* node_b1   = (const float*)d_in[13];
    const float* node_w2   = (const float*)d_in[14];
    const float* node_b2   = (const float*)d_in[15];
    const float* dec_w1    = (const float*)d_in[16];
    const float* dec_b1    = (const float*)d_in[17];
    const float* dec_w2    = (const float*)d_in[18];
    const float* dec_b2    = (const float*)d_in[19];
    const int*   edge_idx  = (const int*)d_in[20];
    // d_in[21] = node_batch: implied by graph id, unused.

    int Etot = in_sizes[20] / 2;
    int Bg   = Etot / NEDGE;

    cudaFuncSetAttribute(DirectPathAttenuationGNN_kernel,
                         cudaFuncAttributeMaxDynamicSharedMemorySize,
                         (int)sizeof(SM));

    DirectPathAttenuationGNN_kernel<<<Bg, NTHREADS, sizeof(SM)>>>(
        x_nodes, damage,
        enc_n_w, enc_n_b, enc_e_w1, enc_e_b1, enc_e_w2, enc_e_b2,
        edge_w1, edge_b1, edge_w2, edge_b2,
        node_w1, node_b1, node_w2, node_b2,
        dec_w1, dec_b1, dec_w2, dec_b2,
        edge_idx, Etot,
        (float*)d_out);
}

// round 2
// speedup vs baseline: 1.3731x; 1.3731x over previous
#include <cuda_runtime.h>
#include <math.h>

#define NSENS 9
#define NEDGE 72
#define NPAIR 36
#define HDIM  128
#define NLAY  4
#define NTHREADS 288      // 9 warps: warp w owns edges 8w..8w+7
#define EPSF 1e-8f
#define EP 132            // padded row stride for edge-feature arrays (floats)
#define HP 132            // padded row stride for node-feature arrays
#define DP 68             // padded row stride for decoder hidden

// ---------------------------------------------------------------------------
// Shared memory (one CTA per graph)
// ---------------------------------------------------------------------------
struct SM {
    float h_n[NSENS * HP];     // node features [9][132]
    float agg[NSENS * HP];     // aggregated sender means
    float h_e[NEDGE * EP];     // edge features [72][132]
    float hid[NEDGE * EP];     // scratch: edge-MLP hidden / node hidden / decoder hidden
    float phys[NEDGE][8];
    float xs[NSENS][2];
    float dmg[2];
    float deg[NSENS];
    float dec[NEDGE];
    int   row_l[NEDGE];
    int   col_l[NEDGE];
    int   senders[NSENS][8];
    int   scnt[NSENS];
};

// ---------------------------------------------------------------------------
// Packed f32x2 helpers
// ---------------------------------------------------------------------------
typedef unsigned long long ull;
__device__ __forceinline__ ull pack2(float x) {
    ull r; asm("mov.b64 %0, {%1, %1};" : "=l"(r) : "f"(x)); return r;
}
__device__ __forceinline__ void ffma2(ull& d, ull a, ull b) {
    asm("fma.rn.f32x2 %0, %1, %2, %0;" : "+l"(d) : "l"(a), "l"(b));
}
__device__ __forceinline__ float2 unpack2(ull v) {
    float lo, hi; asm("mov.b64 {%0, %1}, %2;" : "=f"(lo), "=f"(hi) : "l"(v));
    return make_float2(lo, hi);
}

// One k-step: 4 edge-splats x 4 col-pairs = 16 FFMA2
#define GSTEP(AX, W0, W1) do {                                             \
    ull s0 = pack2(av0.AX), s1 = pack2(av1.AX);                            \
    ull s2 = pack2(av2.AX), s3 = pack2(av3.AX);                            \
    ffma2(acc[0][0], s0, (W0).x); ffma2(acc[0][1], s0, (W0).y);            \
    ffma2(acc[0][2], s0, (W1).x); ffma2(acc[0][3], s0, (W1).y);            \
    ffma2(acc[1][0], s1, (W0).x); ffma2(acc[1][1], s1, (W0).y);            \
    ffma2(acc[1][2], s1, (W1).x); ffma2(acc[1][3], s1, (W1).y);            \
    ffma2(acc[2][0], s2, (W0).x); ffma2(acc[2][1], s2, (W0).y);            \
    ffma2(acc[2][2], s2, (W1).x); ffma2(acc[2][3], s2, (W1).y);            \
    ffma2(acc[3][0], s3, (W0).x); ffma2(acc[3][1], s3, (W0).y);            \
    ffma2(acc[3][2], s3, (W1).x); ffma2(acc[3][3], s3, (W1).y);            \
} while (0)

// Accumulate A[4 rows x 128] @ W[128 x 128] into acc (thread owns 4 rows x 8 cols)
__device__ __forceinline__ void tile_fma_seg(
    const float* __restrict__ W,
    const float* __restrict__ A0, const float* __restrict__ A1,
    const float* __restrict__ A2, const float* __restrict__ A3,
    ull (&acc)[4][4], int c16)
{
    const float* wp = W + (c16 << 3);
#pragma unroll 1
    for (int kb = 0; kb < HDIM; kb += 4) {
        float4 av0 = *(const float4*)(A0 + kb);
        float4 av1 = *(const float4*)(A1 + kb);
        float4 av2 = *(const float4*)(A2 + kb);
        float4 av3 = *(const float4*)(A3 + kb);
        const float* wk = wp + kb * HDIM;
        ulonglong2 wa0 = *(const ulonglong2*)(wk);
        ulonglong2 wa1 = *(const ulonglong2*)(wk + 4);
        ulonglong2 wb0 = *(const ulonglong2*)(wk + HDIM);
        ulonglong2 wb1 = *(const ulonglong2*)(wk + HDIM + 4);
        GSTEP(x, wa0, wa1);
        wa0 = *(const ulonglong2*)(wk + 2 * HDIM);
        wa1 = *(const ulonglong2*)(wk + 2 * HDIM + 4);
        GSTEP(y, wb0, wb1);
        wb0 = *(const ulonglong2*)(wk + 3 * HDIM);
        wb1 = *(const ulonglong2*)(wk + 3 * HDIM + 4);
        GSTEP(z, wa0, wa1);
        GSTEP(w, wb0, wb1);
    }
}

// Epilogue: 0 = relu store, 1 = residual add, 2 = plain store
template <int EPI>
__device__ __forceinline__ void tile_epi(
    ull (&acc)[4][4], const float* __restrict__ bias,
    float* __restrict__ O, int ebase, int c16)
{
    float4 bb0 = *(const float4*)(bias + (c16 << 3));
    float4 bb1 = *(const float4*)(bias + (c16 << 3) + 4);
#pragma unroll
    for (int j = 0; j < 4; ++j) {
        float* orow = O + (ebase + j) * EP + (c16 << 3);
        float2 p0 = unpack2(acc[j][0]), p1 = unpack2(acc[j][1]);
        float2 p2 = unpack2(acc[j][2]), p3 = unpack2(acc[j][3]);
        float4 lo = make_float4(p0.x + bb0.x, p0.y + bb0.y, p1.x + bb0.z, p1.y + bb0.w);
        float4 hi = make_float4(p2.x + bb1.x, p2.y + bb1.y, p3.x + bb1.z, p3.y + bb1.w);
        if (EPI == 0) {
            lo = make_float4(fmaxf(lo.x, 0.f), fmaxf(lo.y, 0.f), fmaxf(lo.z, 0.f), fmaxf(lo.w, 0.f));
            hi = make_float4(fmaxf(hi.x, 0.f), fmaxf(hi.y, 0.f), fmaxf(hi.z, 0.f), fmaxf(hi.w, 0.f));
        } else if (EPI == 1) {
            float4 r0 = *(const float4*)orow;
            float4 r1 = *(const float4*)(orow + 4);
            lo = make_float4(lo.x + r0.x, lo.y + r0.y, lo.z + r0.z, lo.w + r0.w);
            hi = make_float4(hi.x + r1.x, hi.y + r1.y, hi.z + r1.z, hi.w + r1.w);
        }
        *(float4*)orow = lo;
        *(float4*)(orow + 4) = hi;
    }
}

// ---------------------------------------------------------------------------
// Fused GNN kernel: one CTA per graph, 288 threads (9 warps)
// ---------------------------------------------------------------------------
__global__ __launch_bounds__(NTHREADS, 2)
void DirectPathAttenuationGNN_kernel(
    const float* __restrict__ x_nodes, const float* __restrict__ damage,
    const float* __restrict__ enc_n_w, const float* __restrict__ enc_n_b,
    const float* __restrict__ enc_e_w1, const float* __restrict__ enc_e_b1,
    const float* __restrict__ enc_e_w2, const float* __restrict__ enc_e_b2,
    const float* __restrict__ edge_w1, const float* __restrict__ edge_b1,
    const float* __restrict__ edge_w2, const float* __restrict__ edge_b2,
    const float* __restrict__ node_w1, const float* __restrict__ node_b1,
    const float* __restrict__ node_w2, const float* __restrict__ node_b2,
    const float* __restrict__ dec_w1, const float* __restrict__ dec_b1,
    const float* __restrict__ dec_w2, const float* __restrict__ dec_b2,
    const int* __restrict__ edge_index, int Etot,
    float* __restrict__ out)
{
    extern __shared__ unsigned char smem_raw[];
    SM& sm = *reinterpret_cast<SM*>(smem_raw);

    const int g    = blockIdx.x;
    const int tid  = threadIdx.x;
    const int wid  = tid >> 5;
    const int lane = tid & 31;
    const int c16  = lane & 15;                       // col group (8 cols)
    const int ebase = (wid << 3) + ((lane >> 4) << 2); // 4 edges of this thread

    // ---- per-graph inputs -------------------------------------------------
    if (tid < NEDGE) {
        int ge = g * NEDGE + tid;
        sm.row_l[tid] = edge_index[ge]        - g * NSENS;
        sm.col_l[tid] = edge_index[Etot + ge] - g * NSENS;
    }
    if (tid < NSENS * 2) ((float*)sm.xs)[tid] = x_nodes[g * NSENS * 2 + tid];
    if (tid < 2)         sm.dmg[tid] = damage[g * 2 + tid];
    __syncthreads();

    // ---- sender lists + degree -------------------------------------------
    if (tid < NSENS) {
        int cnt = 0;
        for (int e = 0; e < NEDGE; ++e)
            if (sm.col_l[e] == tid) { if (cnt < 8) sm.senders[tid][cnt] = sm.row_l[e]; ++cnt; }
        sm.scnt[tid] = cnt < 8 ? cnt : 8;
        sm.deg[tid]  = fmaxf((float)cnt, 1.0f);
    }

    // ---- physical edge features ------------------------------------------
    if (tid < NEDGE) {
        int r = sm.row_l[tid], c = sm.col_l[tid];
        float sx = sm.xs[r][0], sy = sm.xs[r][1];
        float dx = sm.xs[c][0], dy = sm.xs[c][1];
        float g0 = sm.dmg[0],   g1 = sm.dmg[1];
        float vx = sx - dx, vy = sy - dy;
        float elen = sqrtf(vx * vx + vy * vy + EPSF);
        float d21x = -vx, d21y = -vy;
        float l2 = fmaxf(d21x * d21x + d21y * d21y, EPSF);
        float mx = g0 - sx, my = g1 - sy;
        float t = fminf(fmaxf((mx * d21x + my * d21y) / l2, 0.f), 1.f);
        float px = sx + t * d21x, py = sy + t * d21y;
        float qx = g0 - px, qy = g1 - py;
        float d_path = sqrtf(qx * qx + qy * qy + EPSF);
        float d_tx = sqrtf(mx * mx + my * my + EPSF);
        float rx = dx - g0, ry = dy - g1;
        float d_rx = sqrtf(rx * rx + ry * ry + EPSF);
        sm.phys[tid][0] = vx;   sm.phys[tid][1] = vy;
        sm.phys[tid][2] = elen; sm.phys[tid][3] = d_path;
        sm.phys[tid][4] = d_tx; sm.phys[tid][5] = d_rx;
    }

    // ---- node encoder (K=2): h_n = x @ Wn + bn ----------------------------
    {
        int n = tid >> 5, c4 = lane;  // 9 warps x 32 lanes = 288 = 9*32
        float x0 = sm.xs[n][0], x1 = sm.xs[n][1];
        float4 w0 = *(const float4*)(enc_n_w + (c4 << 2));
        float4 w1 = *(const float4*)(enc_n_w + HDIM + (c4 << 2));
        float4 b  = *(const float4*)(enc_n_b + (c4 << 2));
        float4 o  = make_float4(fmaf(x1, w1.x, fmaf(x0, w0.x, b.x)),
                                fmaf(x1, w1.y, fmaf(x0, w0.y, b.y)),
                                fmaf(x1, w1.z, fmaf(x0, w0.z, b.z)),
                                fmaf(x1, w1.w, fmaf(x0, w0.w, b.w)));
        *(float4*)&sm.h_n[n * HP + (c4 << 2)] = o;
    }
    __syncthreads();

    // ---- edge encoder hidden (K=6) -> hid ---------------------------------
    for (int idx = tid; idx < NEDGE * 32; idx += NTHREADS) {
        int e = idx >> 5, c4 = idx & 31;
        float4 a = *(const float4*)(enc_e_b1 + (c4 << 2));
#pragma unroll
        for (int k = 0; k < 6; ++k) {
            float p = sm.phys[e][k];
            float4 wv = *(const float4*)(enc_e_w1 + k * HDIM + (c4 << 2));
            a.x = fmaf(p, wv.x, a.x); a.y = fmaf(p, wv.y, a.y);
            a.z = fmaf(p, wv.z, a.z); a.w = fmaf(p, wv.w, a.w);
        }
        *(float4*)&sm.hid[e * EP + (c4 << 2)] =
            make_float4(fmaxf(a.x, 0.f), fmaxf(a.y, 0.f), fmaxf(a.z, 0.f), fmaxf(a.w, 0.f));
    }
    __syncthreads();

    // ---- edge encoder out: h_e = hid @ W2 + b2 ----------------------------
    {
        ull acc[4][4];
#pragma unroll
        for (int j = 0; j < 4; ++j)
#pragma unroll
            for (int p = 0; p < 4; ++p) acc[j][p] = 0ull;
        tile_fma_seg(enc_e_w2,
                     sm.hid + (ebase + 0) * EP, sm.hid + (ebase + 1) * EP,
                     sm.hid + (ebase + 2) * EP, sm.hid + (ebase + 3) * EP,
                     acc, c16);
        tile_epi<2>(acc, enc_e_b2, sm.h_e, ebase, c16);
    }
    __syncthreads();

    // ---- 4 message-passing layers -----------------------------------------
    for (int l = 0; l < NLAY; ++l) {
        const float* w1  = edge_w1 + l * 3 * HDIM * HDIM;
        const float* b1  = edge_b1 + l * HDIM;
        const float* w2  = edge_w2 + l * HDIM * HDIM;
        const float* b2  = edge_b2 + l * HDIM;
        const float* nw1 = node_w1 + l * 2 * HDIM * HDIM;
        const float* nb1 = node_b1 + l * HDIM;
        const float* nw2 = node_w2 + l * HDIM * HDIM;
        const float* nb2 = node_b2 + l * HDIM;

        // --- edge MLP: hid = relu([h_n[row],h_n[col],h_e] @ w1 + b1) -------
        {
            ull acc[4][4];
#pragma unroll
            for (int j = 0; j < 4; ++j)
#pragma unroll
                for (int p = 0; p < 4; ++p) acc[j][p] = 0ull;
            // segment 0: h_n[row]
            tile_fma_seg(w1,
                         sm.h_n + sm.row_l[ebase + 0] * HP, sm.h_n + sm.row_l[ebase + 1] * HP,
                         sm.h_n + sm.row_l[ebase + 2] * HP, sm.h_n + sm.row_l[ebase + 3] * HP,
                         acc, c16);
            // segment 1: h_n[col]
            tile_fma_seg(w1 + HDIM * HDIM,
                         sm.h_n + sm.col_l[ebase + 0] * HP, sm.h_n + sm.col_l[ebase + 1] * HP,
                         sm.h_n + sm.col_l[ebase + 2] * HP, sm.h_n + sm.col_l[ebase + 3] * HP,
                         acc, c16);
            // segment 2: h_e
            tile_fma_seg(w1 + 2 * HDIM * HDIM,
                         sm.h_e + (ebase + 0) * EP, sm.h_e + (ebase + 1) * EP,
                         sm.h_e + (ebase + 2) * EP, sm.h_e + (ebase + 3) * EP,
                         acc, c16);
            tile_epi<0>(acc, b1, sm.hid, ebase, c16);
        }
        __syncwarp();   // hid rows are half-warp private; reader is same half-warp set
        // --- h_e += hid @ w2 + b2 -----------------------------------------
        {
            ull acc[4][4];
#pragma unroll
            for (int j = 0; j < 4; ++j)
#pragma unroll
                for (int p = 0; p < 4; ++p) acc[j][p] = 0ull;
            tile_fma_seg(w2,
                         sm.hid + (ebase + 0) * EP, sm.hid + (ebase + 1) * EP,
                         sm.hid + (ebase + 2) * EP, sm.hid + (ebase + 3) * EP,
                         acc, c16);
            tile_epi<1>(acc, b2, sm.h_e, ebase, c16);
        }
        __syncthreads();

        // --- mean aggregation ---------------------------------------------
        for (int idx = tid; idx < NSENS * HDIM; idx += NTHREADS) {
            int n = idx >> 7, h = idx & 127;
            float s = 0.f;
            int c = sm.scnt[n];
            for (int i = 0; i < c; ++i) s += sm.h_n[sm.senders[n][i] * HP + h];
            sm.agg[n * HP + h] = s / sm.deg[n];
        }
        __syncthreads();

        // --- node MLP hidden (K=256) -> nhid (alias hid) -------------------
        {
            int n = tid >> 5, c4 = lane;
            const float* w = nw1 + (c4 << 2);
            ull a0 = 0ull, a1 = 0ull;
#pragma unroll 4
            for (int k = 0; k < HDIM; ++k) {
                ull s = pack2(sm.h_n[n * HP + k]);
                ulonglong2 wv = *(const ulonglong2*)(w + k * HDIM);
                ffma2(a0, s, wv.x); ffma2(a1, s, wv.y);
            }
#pragma unroll 4
            for (int k = 0; k < HDIM; ++k) {
                ull s = pack2(sm.agg[n * HP + k]);
                ulonglong2 wv = *(const ulonglong2*)(w + (HDIM + k) * HDIM);
                ffma2(a0, s, wv.x); ffma2(a1, s, wv.y);
            }
            float4 b = *(const float4*)(nb1 + (c4 << 2));
            float2 p0 = unpack2(a0), p1 = unpack2(a1);
            __syncthreads();   // hid readers (gemm2) done before overwrite
            *(float4*)&sm.hid[n * EP + (c4 << 2)] =
                make_float4(fmaxf(p0.x + b.x, 0.f), fmaxf(p0.y + b.y, 0.f),
                            fmaxf(p1.x + b.z, 0.f), fmaxf(p1.y + b.w, 0.f));
        }
        __syncthreads();

        // --- h_n += nhid @ nw2 + nb2 --------------------------------------
        {
            int n = tid >> 5, c4 = lane;
            const float* w = nw2 + (c4 << 2);
            ull a0 = 0ull, a1 = 0ull;
#pragma unroll 4
            for (int k = 0; k < HDIM; ++k) {
                ull s = pack2(sm.hid[n * EP + k]);
                ulonglong2 wv = *(const ulonglong2*)(w + k * HDIM);
                ffma2(a0, s, wv.x); ffma2(a1, s, wv.y);
            }
            float4 b = *(const float4*)(nb2 + (c4 << 2));
            float2 p0 = unpack2(a0), p1 = unpack2(a1);
            float4* hp = (float4*)&sm.h_n[n * HP + (c4 << 2)];
            float4 old = *hp;
            *hp = make_float4(old.x + p0.x + b.x, old.y + p0.y + b.y,
                              old.z + p1.x + b.z, old.w + p1.y + b.w);
        }
        __syncthreads();
    }

    // ---- decoder hidden: dhid = relu(h_e @ dec_w1 + dec_b1) ---------------
    float* dhid = sm.hid;   // [72][DP]
#pragma unroll
    for (int r = 0; r < 4; ++r) {
        int idx = tid + r * NTHREADS;          // 4*288 = 1152 = 72*16
        int e = idx >> 4, c4 = idx & 15;
        const float* w = dec_w1 + (c4 << 2);
        ull a0 = 0ull, a1 = 0ull;
#pragma unroll 4
        for (int k = 0; k < HDIM; ++k) {
            ull s = pack2(sm.h_e[e * EP + k]);
            ulonglong2 wv = *(const ulonglong2*)(w + k * 64);
            ffma2(a0, s, wv.x); ffma2(a1, s, wv.y);
        }
        float4 b = *(const float4*)(dec_b1 + (c4 << 2));
        float2 p0 = unpack2(a0), p1 = unpack2(a1);
        if (r == 0) __syncthreads();           // all threads hit this once (uniform)
        *(float4*)&dhid[e * DP + (c4 << 2)] =
            make_float4(fmaxf(p0.x + b.x, 0.f), fmaxf(p0.y + b.y, 0.f),
                        fmaxf(p1.x + b.z, 0.f), fmaxf(p1.y + b.w, 0.f));
    }
    __syncthreads();

    // ---- decoder out + sigmoid -------------------------------------------
    if (tid < NEDGE) {
        float a = dec_b2[0];
#pragma unroll 4
        for (int k = 0; k < 64; ++k) a = fmaf(dhid[tid * DP + k], dec_w2[k], a);
        sm.dec[tid] = 1.f / (1.f + expf(-a));
    }
    __syncthreads();
    if (tid < NPAIR)
        out[g * NPAIR + tid] = 0.5f * (sm.dec[2 * tid] + sm.dec[2 * tid + 1]);
}

// ---------------------------------------------------------------------------
// Harness entry point
// ---------------------------------------------------------------------------
extern "C" void kernel_launch(void* const* d_in, const int* in_sizes, int n_in,
                              void* d_out, int out_size)
{
    const float* x_nodes   = (const float*)d_in[0];
    const float* damage    = (const float*)d_in[1];
    const float* enc_n_w   = (const float*)d_in[2];
    const float* enc_n_b   = (const float*)d_in[3];
    const float* enc_e_w1  = (const float*)d_in[4];
    const float* enc_e_b1  = (const float*)d_in[5];
    const float* enc_e_w2  = (const float*)d_in[6];
    const float* enc_e_b2  = (const float*)d_in[7];
    const float* edge_w1   = (const float*)d_in[8];
    const float* edge_b1   = (const float*)d_in[9];
    const float* edge_w2   = (const float*)d_in[10];
    const float* edge_b2   = (const float*)d_in[11];
    const float* node_w1   = (const float*)d_in[12];
    const float* node_b1   = (const float*)d_in[13];
    const float* node_w2   = (const float*)d_in[14];
    const float* node_b2   = (const float*)d_in[15];
    const float* dec_w1    = (const float*)d_in[16];
    const float* dec_b1    = (const float*)d_in[17];
    const float* dec_w2    = (const float*)d_in[18];
    const float* dec_b2    = (const float*)d_in[19];
    const int*   edge_idx  = (const int*)d_in[20];

    int Etot = in_sizes[20] / 2;
    int Bg   = Etot / NEDGE;

    cudaFuncSetAttribute(DirectPathAttenuationGNN_kernel,
                         cudaFuncAttributeMaxDynamicSharedMemorySize,
                         (int)sizeof(SM));

    DirectPathAttenuationGNN_kernel<<<Bg, NTHREADS, sizeof(SM)>>>(
        x_nodes, damage,
        enc_n_w, enc_n_b, enc_e_w1, enc_e_b1, enc_e_w2, enc_e_b2,
        edge_w1, edge_b1, edge_w2, edge_b2,
        node_w1, node_b1, node_w2, node_b2,
        dec_w1, dec_b1, dec_w2, dec_b2,
        edge_idx, Etot,
        (float*)d_out);
}

// round 3
// speedup vs baseline: 1.5576x; 1.1344x over previous
#include <cuda_runtime.h>
#include <math.h>

#define NSENS 9
#define NEDGE 72
#define NPAIR 36
#define HDIM  128
#define NLAY  4
#define NTHREADS 320      // 10 warps: 0-7 edge GEMMs, 8-9 node-side work
#define EPSF 1e-8f
#define EP 132
#define HP 132
#define DP 68

typedef unsigned long long ull;

// ---------------------------------------------------------------------------
// Shared memory (one CTA per graph)
// ---------------------------------------------------------------------------
struct SM {
    float h_n[NSENS * HP];
    float agg[NSENS * HP];
    float Pm [NSENS * HP];    // P = h_n @ W1a
    float Qm [NSENS * HP];    // Q = h_n @ W1b
    float nhid[NSENS * HP];   // node-MLP hidden
    float h_e[NEDGE * EP];
    float hid[NEDGE * EP];    // edge-MLP hidden / encoder hidden / decoder hidden
    float phys[NEDGE][8];
    float xs[NSENS][2];
    float dmg[2];
    float invdeg[NSENS];
    float dec[NEDGE];
    int   row_l[NEDGE];
    int   col_l[NEDGE];
    int   senders[NSENS][8];
    int   scnt[NSENS];
};

// ---------------------------------------------------------------------------
// Packed f32x2 helpers
// ---------------------------------------------------------------------------
__device__ __forceinline__ ull pack2(float x) {
    ull r; asm("mov.b64 %0, {%1, %1};" : "=l"(r) : "f"(x)); return r;
}
__device__ __forceinline__ void ffma2(ull& d, ull a, ull b) {
    asm("fma.rn.f32x2 %0, %1, %2, %0;" : "+l"(d) : "l"(a), "l"(b));
}
__device__ __forceinline__ float2 unpack2(ull v) {
    float lo, hi; asm("mov.b64 {%0, %1}, %2;" : "=f"(lo), "=f"(hi) : "l"(v));
    return make_float2(lo, hi);
}

#define ZERO5(A) do {                                                       \
    _Pragma("unroll") for (int _j = 0; _j < 5; ++_j)                        \
    _Pragma("unroll") for (int _p = 0; _p < 4; ++_p) (A)[_j][_p] = 0ull;    \
} while (0)

// 5 row-splats x 4 col-pairs = 20 FFMA2
#define STEP5(AX, W0, W1) do {                                              \
    ull s0 = pack2(v0.AX), s1 = pack2(v1.AX), s2 = pack2(v2.AX);            \
    ull s3 = pack2(v3.AX), s4 = pack2(v4.AX);                               \
    ffma2(acc[0][0], s0, (W0).x); ffma2(acc[0][1], s0, (W0).y);             \
    ffma2(acc[0][2], s0, (W1).x); ffma2(acc[0][3], s0, (W1).y);             \
    ffma2(acc[1][0], s1, (W0).x); ffma2(acc[1][1], s1, (W0).y);             \
    ffma2(acc[1][2], s1, (W1).x); ffma2(acc[1][3], s1, (W1).y);             \
    ffma2(acc[2][0], s2, (W0).x); ffma2(acc[2][1], s2, (W0).y);             \
    ffma2(acc[2][2], s2, (W1).x); ffma2(acc[2][3], s2, (W1).y);             \
    ffma2(acc[3][0], s3, (W0).x); ffma2(acc[3][1], s3, (W0).y);             \
    ffma2(acc[3][2], s3, (W1).x); ffma2(acc[3][3], s3, (W1).y);             \
    ffma2(acc[4][0], s4, (W0).x); ffma2(acc[4][1], s4, (W0).y);             \
    ffma2(acc[4][2], s4, (W1).x); ffma2(acc[4][3], s4, (W1).y);             \
} while (0)

// acc[5 rows][8 cols as 4 f32x2] += A(5 rows)[0:K] @ W[K][128] (cols c16*8..+7)
__device__ __forceinline__ void gemm5(
    const float* __restrict__ W, int c16,
    const float* __restrict__ a0, const float* __restrict__ a1,
    const float* __restrict__ a2, const float* __restrict__ a3,
    const float* __restrict__ a4,
    ull (&acc)[5][4], int K)
{
    const float* wp = W + (c16 << 3);
#pragma unroll 1
    for (int kb = 0; kb < K; kb += 4) {
        float4 v0 = *(const float4*)(a0 + kb);
        float4 v1 = *(const float4*)(a1 + kb);
        float4 v2 = *(const float4*)(a2 + kb);
        float4 v3 = *(const float4*)(a3 + kb);
        float4 v4 = *(const float4*)(a4 + kb);
        const float* wk = wp + kb * HDIM;
        ulonglong2 wA0 = *(const ulonglong2*)(wk);
        ulonglong2 wA1 = *(const ulonglong2*)(wk + 4);
        ulonglong2 wB0 = *(const ulonglong2*)(wk + HDIM);
        ulonglong2 wB1 = *(const ulonglong2*)(wk + HDIM + 4);
        STEP5(x, wA0, wA1);
        wA0 = *(const ulonglong2*)(wk + 2 * HDIM);
        wA1 = *(const ulonglong2*)(wk + 2 * HDIM + 4);
        STEP5(y, wB0, wB1);
        wB0 = *(const ulonglong2*)(wk + 3 * HDIM);
        wB1 = *(const ulonglong2*)(wk + 3 * HDIM + 4);
        STEP5(z, wA0, wA1);
        STEP5(w, wB0, wB1);
    }
}

// MODE: 0 = relu(acc+bias), 1 = out += acc+bias, 2 = acc+bias, 3 = acc (no bias)
template<int MODE, bool PQ>
__device__ __forceinline__ void epi5(
    ull (&acc)[5][4], const float* __restrict__ bias, int c16,
    float* __restrict__ outBase, int ostride, const int* r, int nvalid,
    const float* __restrict__ Pb, const float* __restrict__ Qb,
    const int* pr, const int* qr)
{
    const int co = c16 << 3;
    float4 b0 = make_float4(0.f, 0.f, 0.f, 0.f), b1 = b0;
    if (MODE != 3) {
        b0 = *(const float4*)(bias + co);
        b1 = *(const float4*)(bias + co + 4);
    }
#pragma unroll
    for (int j = 0; j < 5; ++j) {
        if (j >= nvalid) break;
        float2 p0 = unpack2(acc[j][0]), p1 = unpack2(acc[j][1]);
        float2 p2 = unpack2(acc[j][2]), p3 = unpack2(acc[j][3]);
        float lo0 = p0.x + b0.x, lo1 = p0.y + b0.y, lo2 = p1.x + b0.z, lo3 = p1.y + b0.w;
        float hi0 = p2.x + b1.x, hi1 = p2.y + b1.y, hi2 = p3.x + b1.z, hi3 = p3.y + b1.w;
        if (PQ) {
            const float* pp = Pb + pr[j] * HP + co;
            const float* qp = Qb + qr[j] * HP + co;
            float4 pa = *(const float4*)pp, pb2 = *(const float4*)(pp + 4);
            float4 qa = *(const float4*)qp, qb2 = *(const float4*)(qp + 4);
            lo0 += pa.x + qa.x; lo1 += pa.y + qa.y; lo2 += pa.z + qa.z; lo3 += pa.w + qa.w;
            hi0 += pb2.x + qb2.x; hi1 += pb2.y + qb2.y; hi2 += pb2.z + qb2.z; hi3 += pb2.w + qb2.w;
        }
        float* o = outBase + r[j] * ostride + co;
        if (MODE == 0) {
            *(float4*)o       = make_float4(fmaxf(lo0,0.f), fmaxf(lo1,0.f), fmaxf(lo2,0.f), fmaxf(lo3,0.f));
            *(float4*)(o + 4) = make_float4(fmaxf(hi0,0.f), fmaxf(hi1,0.f), fmaxf(hi2,0.f), fmaxf(hi3,0.f));
        } else if (MODE == 1) {
            float4 x0 = *(const float4*)o, x1 = *(const float4*)(o + 4);
            *(float4*)o       = make_float4(x0.x + lo0, x0.y + lo1, x0.z + lo2, x0.w + lo3);
            *(float4*)(o + 4) = make_float4(x1.x + hi0, x1.y + hi1, x1.z + hi2, x1.w + hi3);
        } else {
            *(float4*)o       = make_float4(lo0, lo1, lo2, lo3);
            *(float4*)(o + 4) = make_float4(hi0, hi1, hi2, hi3);
        }
    }
}

// ---------------------------------------------------------------------------
// Fused GNN kernel: one CTA per graph, 320 threads (10 warps)
// ---------------------------------------------------------------------------
__global__ __launch_bounds__(NTHREADS, 2)
void DirectPathAttenuationGNN_kernel(
    const float* __restrict__ x_nodes, const float* __restrict__ damage,
    const float* __restrict__ enc_n_w, const float* __restrict__ enc_n_b,
    const float* __restrict__ enc_e_w1, const float* __restrict__ enc_e_b1,
    const float* __restrict__ enc_e_w2, const float* __restrict__ enc_e_b2,
    const float* __restrict__ edge_w1, const float* __restrict__ edge_b1,
    const float* __restrict__ edge_w2, const float* __restrict__ edge_b2,
    const float* __restrict__ node_w1, const float* __restrict__ node_b1,
    const float* __restrict__ node_w2, const float* __restrict__ node_b2,
    const float* __restrict__ dec_w1, const float* __restrict__ dec_b1,
    const float* __restrict__ dec_w2, const float* __restrict__ dec_b2,
    const int* __restrict__ edge_index, int Etot,
    float* __restrict__ out)
{
    extern __shared__ unsigned char smem_raw[];
    SM& sm = *reinterpret_cast<SM*>(smem_raw);

    const int g    = blockIdx.x;
    const int tid  = threadIdx.x;
    const int wid  = tid >> 5;
    const int lane = tid & 31;
    const int hw   = lane >> 4;      // half-warp
    const int c16  = lane & 15;      // 8-col group within 128

    // edge rows for warps 0-7 (9 edges per warp; half0 rows 0-4, half1 rows 5-8)
    int er[5]; int evalid = hw ? 4 : 5;
    {
        int base = wid * 9 + hw * 5, last = wid * 9 + 8;
#pragma unroll
        for (int j = 0; j < 5; ++j) { int r = base + j; er[j] = r < last ? r : last; }
    }
    // node rows for warps 8-9
    int nr[5]; int nvalid = hw ? 4 : 5;
    {
        int base = hw * 5;
#pragma unroll
        for (int j = 0; j < 5; ++j) { int r = base + j; nr[j] = r < 8 ? r : 8; }
    }

    // ---- per-graph inputs -------------------------------------------------
    if (tid < NEDGE) {
        int ge = g * NEDGE + tid;
        sm.row_l[tid] = edge_index[ge]        - g * NSENS;
        sm.col_l[tid] = edge_index[Etot + ge] - g * NSENS;
    }
    if (tid < NSENS * 2) ((float*)sm.xs)[tid] = x_nodes[g * NSENS * 2 + tid];
    if (tid < 2)         sm.dmg[tid] = damage[g * 2 + tid];
    __syncthreads();

    // ---- sender lists + degree -------------------------------------------
    if (tid < NSENS) {
        int cnt = 0;
        for (int e = 0; e < NEDGE; ++e)
            if (sm.col_l[e] == tid) { if (cnt < 8) sm.senders[tid][cnt] = sm.row_l[e]; ++cnt; }
        sm.scnt[tid]   = cnt < 8 ? cnt : 8;
        sm.invdeg[tid] = 1.0f / fmaxf((float)cnt, 1.0f);
    }

    // ---- physical edge features ------------------------------------------
    if (tid < NEDGE) {
        int r = sm.row_l[tid], c = sm.col_l[tid];
        float sx = sm.xs[r][0], sy = sm.xs[r][1];
        float dx = sm.xs[c][0], dy = sm.xs[c][1];
        float g0 = sm.dmg[0],   g1 = sm.dmg[1];
        float vx = sx - dx, vy = sy - dy;
        float elen = sqrtf(vx * vx + vy * vy + EPSF);
        float d21x = -vx, d21y = -vy;
        float l2 = fmaxf(d21x * d21x + d21y * d21y, EPSF);
        float mx = g0 - sx, my = g1 - sy;
        float t = fminf(fmaxf((mx * d21x + my * d21y) / l2, 0.f), 1.f);
        float px = sx + t * d21x, py = sy + t * d21y;
        float qx = g0 - px, qy = g1 - py;
        float d_path = sqrtf(qx * qx + qy * qy + EPSF);
        float d_tx = sqrtf(mx * mx + my * my + EPSF);
        float rx = dx - g0, ry = dy - g1;
        float d_rx = sqrtf(rx * rx + ry * ry + EPSF);
        sm.phys[tid][0] = vx;   sm.phys[tid][1] = vy;
        sm.phys[tid][2] = elen; sm.phys[tid][3] = d_path;
        sm.phys[tid][4] = d_tx; sm.phys[tid][5] = d_rx;
    }

    // ---- node encoder (K=2) ----------------------------------------------
    if (tid < NSENS * 32) {
        int n = tid >> 5, c4 = lane;
        float x0 = sm.xs[n][0], x1 = sm.xs[n][1];
        float4 w0 = *(const float4*)(enc_n_w + (c4 << 2));
        float4 w1 = *(const float4*)(enc_n_w + HDIM + (c4 << 2));
        float4 b  = *(const float4*)(enc_n_b + (c4 << 2));
        *(float4*)&sm.h_n[n * HP + (c4 << 2)] =
            make_float4(fmaf(x1, w1.x, fmaf(x0, w0.x, b.x)),
                        fmaf(x1, w1.y, fmaf(x0, w0.y, b.y)),
                        fmaf(x1, w1.z, fmaf(x0, w0.z, b.z)),
                        fmaf(x1, w1.w, fmaf(x0, w0.w, b.w)));
    }
    __syncthreads();

    // ---- edge encoder hidden (K=6) -> hid ---------------------------------
    for (int idx = tid; idx < NEDGE * 32; idx += NTHREADS) {
        int e = idx >> 5, c4 = idx & 31;
        float4 a = *(const float4*)(enc_e_b1 + (c4 << 2));
#pragma unroll
        for (int k = 0; k < 6; ++k) {
            float p = sm.phys[e][k];
            float4 wv = *(const float4*)(enc_e_w1 + k * HDIM + (c4 << 2));
            a.x = fmaf(p, wv.x, a.x); a.y = fmaf(p, wv.y, a.y);
            a.z = fmaf(p, wv.z, a.z); a.w = fmaf(p, wv.w, a.w);
        }
        *(float4*)&sm.hid[e * EP + (c4 << 2)] =
            make_float4(fmaxf(a.x, 0.f), fmaxf(a.y, 0.f), fmaxf(a.z, 0.f), fmaxf(a.w, 0.f));
    }
    __syncthreads();

    // ---- edge encoder out: h_e = hid @ W2 + b2 (warps 0-7) ----------------
    if (wid < 8) {
        ull acc[5][4]; ZERO5(acc);
        gemm5(enc_e_w2, c16,
              sm.hid + er[0] * EP, sm.hid + er[1] * EP, sm.hid + er[2] * EP,
              sm.hid + er[3] * EP, sm.hid + er[4] * EP, acc, HDIM);
        epi5<2, false>(acc, enc_e_b2, c16, sm.h_e, EP, er, evalid,
                       nullptr, nullptr, nullptr, nullptr);
    }
    __syncthreads();

    // ---- 4 message-passing layers -----------------------------------------
    for (int l = 0; l < NLAY; ++l) {
        const float* w1  = edge_w1 + l * 3 * HDIM * HDIM;
        const float* b1  = edge_b1 + l * HDIM;
        const float* w2  = edge_w2 + l * HDIM * HDIM;
        const float* b2  = edge_b2 + l * HDIM;
        const float* nw1 = node_w1 + l * 2 * HDIM * HDIM;
        const float* nb1 = node_b1 + l * HDIM;
        const float* nw2 = node_w2 + l * HDIM * HDIM;
        const float* nb2 = node_b2 + l * HDIM;

        ull acc[5][4];   // edge warps' R = h_e @ W1c accumulator (lives across barrier)

        // ===== phase A =====
        if (wid < 8) {
            ZERO5(acc);
            gemm5(w1 + 2 * HDIM * HDIM, c16,
                  sm.h_e + er[0] * EP, sm.h_e + er[1] * EP, sm.h_e + er[2] * EP,
                  sm.h_e + er[3] * EP, sm.h_e + er[4] * EP, acc, HDIM);
        } else if (wid == 8) {
            // P = h_n @ W1a ; Q = h_n @ W1b   (no bias)
            ull pa[5][4]; ZERO5(pa);
            gemm5(w1, c16,
                  sm.h_n + nr[0] * HP, sm.h_n + nr[1] * HP, sm.h_n + nr[2] * HP,
                  sm.h_n + nr[3] * HP, sm.h_n + nr[4] * HP, pa, HDIM);
            epi5<3, false>(pa, nullptr, c16, sm.Pm, HP, nr, nvalid,
                           nullptr, nullptr, nullptr, nullptr);
            ZERO5(pa);
            gemm5(w1 + HDIM * HDIM, c16,
                  sm.h_n + nr[0] * HP, sm.h_n + nr[1] * HP, sm.h_n + nr[2] * HP,
                  sm.h_n + nr[3] * HP, sm.h_n + nr[4] * HP, pa, HDIM);
            epi5<3, false>(pa, nullptr, c16, sm.Qm, HP, nr, nvalid,
                           nullptr, nullptr, nullptr, nullptr);
        } else { // wid == 9: agg then nhid
            for (int n = 0; n < NSENS; ++n) {
                float4 s = make_float4(0.f, 0.f, 0.f, 0.f);
                int c = sm.scnt[n];
                for (int i = 0; i < c; ++i) {
                    float4 v = *(const float4*)&sm.h_n[sm.senders[n][i] * HP + (lane << 2)];
                    s.x += v.x; s.y += v.y; s.z += v.z; s.w += v.w;
                }
                float iv = sm.invdeg[n];
                *(float4*)&sm.agg[n * HP + (lane << 2)] =
                    make_float4(s.x * iv, s.y * iv, s.z * iv, s.w * iv);
            }
            __syncwarp();
            ull na[5][4]; ZERO5(na);
            gemm5(nw1, c16,
                  sm.h_n + nr[0] * HP, sm.h_n + nr[1] * HP, sm.h_n + nr[2] * HP,
                  sm.h_n + nr[3] * HP, sm.h_n + nr[4] * HP, na, HDIM);
            gemm5(nw1 + HDIM * HDIM, c16,
                  sm.agg + nr[0] * HP, sm.agg + nr[1] * HP, sm.agg + nr[2] * HP,
                  sm.agg + nr[3] * HP, sm.agg + nr[4] * HP, na, HDIM);
            epi5<0, false>(na, nb1, c16, sm.nhid, HP, nr, nvalid,
                           nullptr, nullptr, nullptr, nullptr);
        }
        __syncthreads();

        // ===== phase B =====
        if (wid < 8) {
            // hid = relu(R + P[row] + Q[col] + b1)
            int pr[5], qr[5];
#pragma unroll
            for (int j = 0; j < 5; ++j) { pr[j] = sm.row_l[er[j]]; qr[j] = sm.col_l[er[j]]; }
            epi5<0, true>(acc, b1, c16, sm.hid, EP, er, evalid, sm.Pm, sm.Qm, pr, qr);
            __syncwarp();
            // h_e += hid @ W2 + b2
            ull a2[5][4]; ZERO5(a2);
            gemm5(w2, c16,
                  sm.hid + er[0] * EP, sm.hid + er[1] * EP, sm.hid + er[2] * EP,
                  sm.hid + er[3] * EP, sm.hid + er[4] * EP, a2, HDIM);
            epi5<1, false>(a2, b2, c16, sm.h_e, EP, er, evalid,
                           nullptr, nullptr, nullptr, nullptr);
        } else if (wid == 8) {
            // h_n += nhid @ nw2 + nb2
            ull ua[5][4]; ZERO5(ua);
            gemm5(nw2, c16,
                  sm.nhid + nr[0] * HP, sm.nhid + nr[1] * HP, sm.nhid + nr[2] * HP,
                  sm.nhid + nr[3] * HP, sm.nhid + nr[4] * HP, ua, HDIM);
            epi5<1, false>(ua, nb2, c16, sm.h_n, HP, nr, nvalid,
                           nullptr, nullptr, nullptr, nullptr);
        }
        __syncthreads();
    }

    // ---- decoder hidden: dhid = relu(h_e @ dec_w1 + dec_b1) ---------------
    float* dhid = sm.hid;
    for (int idx = tid; idx < NEDGE * 16; idx += NTHREADS) {
        int e = idx >> 4, c4 = idx & 15;
        const float* w = dec_w1 + (c4 << 2);
        ull a0 = 0ull, a1 = 0ull;
#pragma unroll 4
        for (int k = 0; k < HDIM; ++k) {
            ull s = pack2(sm.h_e[e * EP + k]);
            ulonglong2 wv = *(const ulonglong2*)(w + k * 64);
            ffma2(a0, s, wv.x); ffma2(a1, s, wv.y);
        }
        float4 b = *(const float4*)(dec_b1 + (c4 << 2));
        float2 p0 = unpack2(a0), p1 = unpack2(a1);
        *(float4*)&dhid[e * DP + (c4 << 2)] =
            make_float4(fmaxf(p0.x + b.x, 0.f), fmaxf(p0.y + b.y, 0.f),
                        fmaxf(p1.x + b.z, 0.f), fmaxf(p1.y + b.w, 0.f));
    }
    __syncthreads();

    // ---- decoder out + sigmoid -------------------------------------------
    if (tid < NEDGE) {
        float a = dec_b2[0];
#pragma unroll 4
        for (int k = 0; k < 64; ++k) a = fmaf(dhid[tid * DP + k], dec_w2[k], a);
        sm.dec[tid] = 1.f / (1.f + expf(-a));
    }
    __syncthreads();
    if (tid < NPAIR)
        out[g * NPAIR + tid] = 0.5f * (sm.dec[2 * tid] + sm.dec[2 * tid + 1]);
}

// ---------------------------------------------------------------------------
// Harness entry point
// ---------------------------------------------------------------------------
extern "C" void kernel_launch(void* const* d_in, const int* in_sizes, int n_in,
                              void* d_out, int out_size)
{
    const float* x_nodes   = (const float*)d_in[0];
    const float* damage    = (const float*)d_in[1];
    const float* enc_n_w   = (const float*)d_in[2];
    const float* enc_n_b   = (const float*)d_in[3];
    const float* enc_e_w1  = (const float*)d_in[4];
    const float* enc_e_b1  = (const float*)d_in[5];
    const float* enc_e_w2  = (const float*)d_in[6];
    const float* enc_e_b2  = (const float*)d_in[7];
    const float* edge_w1   = (const float*)d_in[8];
    const float* edge_b1   = (const float*)d_in[9];
    const float* edge_w2   = (const float*)d_in[10];
    const float* edge_b2   = (const float*)d_in[11];
    const float* node_w1   = (const float*)d_in[12];
    const float* node_b1   = (const float*)d_in[13];
    const float* node_w2   = (const float*)d_in[14];
    const float* node_b2   = (const float*)d_in[15];
    const float* dec_w1    = (const float*)d_in[16];
    const float* dec_b1    = (const float*)d_in[17];
    const float* dec_w2    = (const float*)d_in[18];
    const float* dec_b2    = (const float*)d_in[19];
    const int*   edge_idx  = (const int*)d_in[20];

    int Etot = in_sizes[20] / 2;
    int Bg   = Etot / NEDGE;

    cudaFuncSetAttribute(DirectPathAttenuationGNN_kernel,
                         cudaFuncAttributeMaxDynamicSharedMemorySize,
                         (int)sizeof(SM));

    DirectPathAttenuationGNN_kernel<<<Bg, NTHREADS, sizeof(SM)>>>(
        x_nodes, damage,
        enc_n_w, enc_n_b, enc_e_w1, enc_e_b1, enc_e_w2, enc_e_b2,
        edge_w1, edge_b1, edge_w2, edge_b2,
        node_w1, node_b1, node_w2, node_b2,
        dec_w1, dec_b1, dec_w2, dec_b2,
        edge_idx, Etot,
        (float*)d_out);
}

// round 4
// speedup vs baseline: 1.9058x; 1.2235x over previous
#include <cuda_runtime.h>
#include <math.h>

#define NSENS 9
#define NEDGE 72
#define NPAIR 36
#define HDIM  128
#define NLAY  4
#define NTHREADS 320      // 10 warps: 0-7 column-tiled edge GEMMs, 8-9 node side
#define EPSF 1e-8f
#define EP 132
#define HP 132
#define DP 68

typedef unsigned long long ull;

// ---------------------------------------------------------------------------
// Shared memory (one CTA per graph)
// ---------------------------------------------------------------------------
struct SM {
    float h_n[NSENS * HP];
    float agg[NSENS * HP];
    float Pm [NSENS * HP];    // P = h_n @ W1a
    float Qm [NSENS * HP];    // Q = h_n @ W1b
    float nhid[NSENS * HP];   // node-MLP hidden
    float h_e[NEDGE * EP];
    float hid[NEDGE * EP];    // edge-MLP hidden / encoder hidden / decoder hidden
    float phys[NEDGE][8];
    float xs[NSENS][2];
    float dmg[2];
    float invdeg[NSENS];
    float dec[NEDGE];
    int   row_l[NEDGE];
    int   col_l[NEDGE];
    int   senders[NSENS][8];
    int   scnt[NSENS];
};

// ---------------------------------------------------------------------------
// Packed f32x2 helpers
// ---------------------------------------------------------------------------
__device__ __forceinline__ ull pack2(float x) {
    ull r; asm("mov.b64 %0, {%1, %1};" : "=l"(r) : "f"(x)); return r;
}
__device__ __forceinline__ void ffma2(ull& d, ull a, ull b) {
    asm("fma.rn.f32x2 %0, %1, %2, %0;" : "+l"(d) : "l"(a), "l"(b));
}
__device__ __forceinline__ float2 unpack2(ull v) {
    float lo, hi; asm("mov.b64 {%0, %1}, %2;" : "=f"(lo), "=f"(hi) : "l"(v));
    return make_float2(lo, hi);
}

#define ZERO9(A) do {                                                       \
    _Pragma("unroll") for (int _j = 0; _j < 9; ++_j)                        \
    { (A)[_j][0] = 0ull; (A)[_j][1] = 0ull; }                               \
} while (0)

#define ZERO5(A) do {                                                       \
    _Pragma("unroll") for (int _j = 0; _j < 5; ++_j)                        \
    _Pragma("unroll") for (int _p = 0; _p < 4; ++_p) (A)[_j][_p] = 0ull;    \
} while (0)

// ---------------------------------------------------------------------------
// Column-tiled 72-row GEMM: warp owns 16 cols, thread owns 9 rows x 4 cols.
//   acc[j] += A[rbase+j][k] * W[k][co..co+3]
// W read once per CTA per GEMM (lanes cg 0..3 cover warp's 16 cols).
// ---------------------------------------------------------------------------
__device__ __forceinline__ void cgemm72(
    const float* __restrict__ W, const float* __restrict__ A,
    int ast, int rbase, int co, ull (&acc)[9][2])
{
    const float* wp = W + co;
    const float* ap = A + rbase * ast;
#pragma unroll 2
    for (int kb = 0; kb < HDIM; kb += 2) {
        ulonglong2 w0 = *(const ulonglong2*)(wp + kb * HDIM);
        ulonglong2 w1 = *(const ulonglong2*)(wp + (kb + 1) * HDIM);
        float2 a[9];
#pragma unroll
        for (int j = 0; j < 9; ++j)
            a[j] = *(const float2*)(ap + j * ast + kb);
#pragma unroll
        for (int j = 0; j < 9; ++j) {
            ull s = pack2(a[j].x);
            ffma2(acc[j][0], s, w0.x);
            ffma2(acc[j][1], s, w0.y);
        }
#pragma unroll
        for (int j = 0; j < 9; ++j) {
            ull s = pack2(a[j].y);
            ffma2(acc[j][0], s, w1.x);
            ffma2(acc[j][1], s, w1.y);
        }
    }
}

// ---------------------------------------------------------------------------
// Row-tiled 5-row GEMM (node-side warps): unchanged from R3
// ---------------------------------------------------------------------------
#define STEP5(AX, W0, W1) do {                                              \
    ull s0 = pack2(v0.AX), s1 = pack2(v1.AX), s2 = pack2(v2.AX);            \
    ull s3 = pack2(v3.AX), s4 = pack2(v4.AX);                               \
    ffma2(acc[0][0], s0, (W0).x); ffma2(acc[0][1], s0, (W0).y);             \
    ffma2(acc[0][2], s0, (W1).x); ffma2(acc[0][3], s0, (W1).y);             \
    ffma2(acc[1][0], s1, (W0).x); ffma2(acc[1][1], s1, (W0).y);             \
    ffma2(acc[1][2], s1, (W1).x); ffma2(acc[1][3], s1, (W1).y);             \
    ffma2(acc[2][0], s2, (W0).x); ffma2(acc[2][1], s2, (W0).y);             \
    ffma2(acc[2][2], s2, (W1).x); ffma2(acc[2][3], s2, (W1).y);             \
    ffma2(acc[3][0], s3, (W0).x); ffma2(acc[3][1], s3, (W0).y);             \
    ffma2(acc[3][2], s3, (W1).x); ffma2(acc[3][3], s3, (W1).y);             \
    ffma2(acc[4][0], s4, (W0).x); ffma2(acc[4][1], s4, (W0).y);             \
    ffma2(acc[4][2], s4, (W1).x); ffma2(acc[4][3], s4, (W1).y);             \
} while (0)

__device__ __forceinline__ void gemm5(
    const float* __restrict__ W, int c16,
    const float* __restrict__ a0, const float* __restrict__ a1,
    const float* __restrict__ a2, const float* __restrict__ a3,
    const float* __restrict__ a4,
    ull (&acc)[5][4], int K)
{
    const float* wp = W + (c16 << 3);
#pragma unroll 1
    for (int kb = 0; kb < K; kb += 4) {
        float4 v0 = *(const float4*)(a0 + kb);
        float4 v1 = *(const float4*)(a1 + kb);
        float4 v2 = *(const float4*)(a2 + kb);
        float4 v3 = *(const float4*)(a3 + kb);
        float4 v4 = *(const float4*)(a4 + kb);
        const float* wk = wp + kb * HDIM;
        ulonglong2 wA0 = *(const ulonglong2*)(wk);
        ulonglong2 wA1 = *(const ulonglong2*)(wk + 4);
        ulonglong2 wB0 = *(const ulonglong2*)(wk + HDIM);
        ulonglong2 wB1 = *(const ulonglong2*)(wk + HDIM + 4);
        STEP5(x, wA0, wA1);
        wA0 = *(const ulonglong2*)(wk + 2 * HDIM);
        wA1 = *(const ulonglong2*)(wk + 2 * HDIM + 4);
        STEP5(y, wB0, wB1);
        wB0 = *(const ulonglong2*)(wk + 3 * HDIM);
        wB1 = *(const ulonglong2*)(wk + 3 * HDIM + 4);
        STEP5(z, wA0, wA1);
        STEP5(w, wB0, wB1);
    }
}

// MODE: 0 = relu(acc+bias), 1 = out += acc+bias, 2 = acc+bias, 3 = acc (raw)
template<int MODE>
__device__ __forceinline__ void epi5(
    ull (&acc)[5][4], const float* __restrict__ bias, int c16,
    float* __restrict__ outBase, int ostride, const int* r, int nvalid)
{
    const int co = c16 << 3;
    float4 b0 = make_float4(0.f, 0.f, 0.f, 0.f), b1 = b0;
    if (MODE != 3) {
        b0 = *(const float4*)(bias + co);
        b1 = *(const float4*)(bias + co + 4);
    }
#pragma unroll
    for (int j = 0; j < 5; ++j) {
        if (j >= nvalid) break;
        float2 p0 = unpack2(acc[j][0]), p1 = unpack2(acc[j][1]);
        float2 p2 = unpack2(acc[j][2]), p3 = unpack2(acc[j][3]);
        float lo0 = p0.x + b0.x, lo1 = p0.y + b0.y, lo2 = p1.x + b0.z, lo3 = p1.y + b0.w;
        float hi0 = p2.x + b1.x, hi1 = p2.y + b1.y, hi2 = p3.x + b1.z, hi3 = p3.y + b1.w;
        float* o = outBase + r[j] * ostride + co;
        if (MODE == 0) {
            *(float4*)o       = make_float4(fmaxf(lo0,0.f), fmaxf(lo1,0.f), fmaxf(lo2,0.f), fmaxf(lo3,0.f));
            *(float4*)(o + 4) = make_float4(fmaxf(hi0,0.f), fmaxf(hi1,0.f), fmaxf(hi2,0.f), fmaxf(hi3,0.f));
        } else if (MODE == 1) {
            float4 x0 = *(const float4*)o, x1 = *(const float4*)(o + 4);
            *(float4*)o       = make_float4(x0.x + lo0, x0.y + lo1, x0.z + lo2, x0.w + lo3);
            *(float4*)(o + 4) = make_float4(x1.x + hi0, x1.y + hi1, x1.z + hi2, x1.w + hi3);
        } else {
            *(float4*)o       = make_float4(lo0, lo1, lo2, lo3);
            *(float4*)(o + 4) = make_float4(hi0, hi1, hi2, hi3);
        }
    }
}

// ---------------------------------------------------------------------------
// Fused GNN kernel: one CTA per graph, 320 threads (10 warps)
// ---------------------------------------------------------------------------
__global__ __launch_bounds__(NTHREADS, 2)
void DirectPathAttenuationGNN_kernel(
    const float* __restrict__ x_nodes, const float* __restrict__ damage,
    const float* __restrict__ enc_n_w, const float* __restrict__ enc_n_b,
    const float* __restrict__ enc_e_w1, const float* __restrict__ enc_e_b1,
    const float* __restrict__ enc_e_w2, const float* __restrict__ enc_e_b2,
    const float* __restrict__ edge_w1, const float* __restrict__ edge_b1,
    const float* __restrict__ edge_w2, const float* __restrict__ edge_b2,
    const float* __restrict__ node_w1, const float* __restrict__ node_b1,
    const float* __restrict__ node_w2, const float* __restrict__ node_b2,
    const float* __restrict__ dec_w1, const float* __restrict__ dec_b1,
    const float* __restrict__ dec_w2, const float* __restrict__ dec_b2,
    const int* __restrict__ edge_index, int Etot,
    float* __restrict__ out)
{
    extern __shared__ unsigned char smem_raw[];
    SM& sm = *reinterpret_cast<SM*>(smem_raw);

    const int g    = blockIdx.x;
    const int tid  = threadIdx.x;
    const int wid  = tid >> 5;
    const int lane = tid & 31;

    // column-tiled layout for edge warps 0-7
    const int rbase = (lane >> 2) * 9;                 // 9 edge rows of this thread
    const int co    = wid * 16 + (lane & 3) * 4;       // 4 output cols

    // row-tiled layout for node warps 8-9
    const int hw  = lane >> 4;
    const int c16 = lane & 15;
    int nr[5]; int nvalid = hw ? 4 : 5;
    {
        int base = hw * 5;
#pragma unroll
        for (int j = 0; j < 5; ++j) { int r = base + j; nr[j] = r < 8 ? r : 8; }
    }

    // ---- per-graph inputs -------------------------------------------------
    if (tid < NEDGE) {
        int ge = g * NEDGE + tid;
        sm.row_l[tid] = edge_index[ge]        - g * NSENS;
        sm.col_l[tid] = edge_index[Etot + ge] - g * NSENS;
    }
    if (tid < NSENS * 2) ((float*)sm.xs)[tid] = x_nodes[g * NSENS * 2 + tid];
    if (tid < 2)         sm.dmg[tid] = damage[g * 2 + tid];
    __syncthreads();

    // ---- sender lists + degree -------------------------------------------
    if (tid < NSENS) {
        int cnt = 0;
        for (int e = 0; e < NEDGE; ++e)
            if (sm.col_l[e] == tid) { if (cnt < 8) sm.senders[tid][cnt] = sm.row_l[e]; ++cnt; }
        sm.scnt[tid]   = cnt < 8 ? cnt : 8;
        sm.invdeg[tid] = 1.0f / fmaxf((float)cnt, 1.0f);
    }

    // ---- physical edge features ------------------------------------------
    if (tid < NEDGE) {
        int r = sm.row_l[tid], c = sm.col_l[tid];
        float sx = sm.xs[r][0], sy = sm.xs[r][1];
        float dx = sm.xs[c][0], dy = sm.xs[c][1];
        float g0 = sm.dmg[0],   g1 = sm.dmg[1];
        float vx = sx - dx, vy = sy - dy;
        float elen = sqrtf(vx * vx + vy * vy + EPSF);
        float d21x = -vx, d21y = -vy;
        float l2 = fmaxf(d21x * d21x + d21y * d21y, EPSF);
        float mx = g0 - sx, my = g1 - sy;
        float t = fminf(fmaxf((mx * d21x + my * d21y) / l2, 0.f), 1.f);
        float px = sx + t * d21x, py = sy + t * d21y;
        float qx = g0 - px, qy = g1 - py;
        float d_path = sqrtf(qx * qx + qy * qy + EPSF);
        float d_tx = sqrtf(mx * mx + my * my + EPSF);
        float rx = dx - g0, ry = dy - g1;
        float d_rx = sqrtf(rx * rx + ry * ry + EPSF);
        sm.phys[tid][0] = vx;   sm.phys[tid][1] = vy;
        sm.phys[tid][2] = elen; sm.phys[tid][3] = d_path;
        sm.phys[tid][4] = d_tx; sm.phys[tid][5] = d_rx;
    }

    // ---- node encoder (K=2) ----------------------------------------------
    if (tid < NSENS * 32) {
        int n = tid >> 5, c4 = lane;
        float x0 = sm.xs[n][0], x1 = sm.xs[n][1];
        float4 w0 = *(const float4*)(enc_n_w + (c4 << 2));
        float4 w1 = *(const float4*)(enc_n_w + HDIM + (c4 << 2));
        float4 b  = *(const float4*)(enc_n_b + (c4 << 2));
        *(float4*)&sm.h_n[n * HP + (c4 << 2)] =
            make_float4(fmaf(x1, w1.x, fmaf(x0, w0.x, b.x)),
                        fmaf(x1, w1.y, fmaf(x0, w0.y, b.y)),
                        fmaf(x1, w1.z, fmaf(x0, w0.z, b.z)),
                        fmaf(x1, w1.w, fmaf(x0, w0.w, b.w)));
    }
    __syncthreads();

    // ---- edge encoder hidden (K=6) -> hid ---------------------------------
    for (int idx = tid; idx < NEDGE * 32; idx += NTHREADS) {
        int e = idx >> 5, c4 = idx & 31;
        float4 a = *(const float4*)(enc_e_b1 + (c4 << 2));
#pragma unroll
        for (int k = 0; k < 6; ++k) {
            float p = sm.phys[e][k];
            float4 wv = *(const float4*)(enc_e_w1 + k * HDIM + (c4 << 2));
            a.x = fmaf(p, wv.x, a.x); a.y = fmaf(p, wv.y, a.y);
            a.z = fmaf(p, wv.z, a.z); a.w = fmaf(p, wv.w, a.w);
        }
        *(float4*)&sm.hid[e * EP + (c4 << 2)] =
            make_float4(fmaxf(a.x, 0.f), fmaxf(a.y, 0.f), fmaxf(a.z, 0.f), fmaxf(a.w, 0.f));
    }
    __syncthreads();

    // ---- edge encoder out: h_e = hid @ W2 + b2 (column-tiled, warps 0-7) --
    if (wid < 8) {
        ull acc[9][2]; ZERO9(acc);
        cgemm72(enc_e_w2, sm.hid, EP, rbase, co, acc);
        float4 b = *(const float4*)(enc_e_b2 + co);
#pragma unroll
        for (int j = 0; j < 9; ++j) {
            float2 p0 = unpack2(acc[j][0]), p1 = unpack2(acc[j][1]);
            *(float4*)&sm.h_e[(rbase + j) * EP + co] =
                make_float4(p0.x + b.x, p0.y + b.y, p1.x + b.z, p1.y + b.w);
        }
    }
    __syncthreads();

    // ---- 4 message-passing layers -----------------------------------------
    for (int l = 0; l < NLAY; ++l) {
        const float* w1  = edge_w1 + l * 3 * HDIM * HDIM;
        const float* b1  = edge_b1 + l * HDIM;
        const float* w2  = edge_w2 + l * HDIM * HDIM;
        const float* b2  = edge_b2 + l * HDIM;
        const float* nw1 = node_w1 + l * 2 * HDIM * HDIM;
        const float* nb1 = node_b1 + l * HDIM;
        const float* nw2 = node_w2 + l * HDIM * HDIM;
        const float* nb2 = node_b2 + l * HDIM;

        ull acc[9][2];   // edge warps' R = h_e @ W1c (held across barrier)

        // ===== phase A =====
        if (wid < 8) {
            ZERO9(acc);
            cgemm72(w1 + 2 * HDIM * HDIM, sm.h_e, EP, rbase, co, acc);
        } else if (wid == 8) {
            // P = h_n @ W1a ; Q = h_n @ W1b
            ull pa[5][4]; ZERO5(pa);
            gemm5(w1, c16,
                  sm.h_n + nr[0] * HP, sm.h_n + nr[1] * HP, sm.h_n + nr[2] * HP,
                  sm.h_n + nr[3] * HP, sm.h_n + nr[4] * HP, pa, HDIM);
            epi5<3>(pa, nullptr, c16, sm.Pm, HP, nr, nvalid);
            ZERO5(pa);
            gemm5(w1 + HDIM * HDIM, c16,
                  sm.h_n + nr[0] * HP, sm.h_n + nr[1] * HP, sm.h_n + nr[2] * HP,
                  sm.h_n + nr[3] * HP, sm.h_n + nr[4] * HP, pa, HDIM);
            epi5<3>(pa, nullptr, c16, sm.Qm, HP, nr, nvalid);
        } else { // wid == 9: agg then node hidden
            for (int n = 0; n < NSENS; ++n) {
                float4 s = make_float4(0.f, 0.f, 0.f, 0.f);
                int c = sm.scnt[n];
                for (int i = 0; i < c; ++i) {
                    float4 v = *(const float4*)&sm.h_n[sm.senders[n][i] * HP + (lane << 2)];
                    s.x += v.x; s.y += v.y; s.z += v.z; s.w += v.w;
                }
                float iv = sm.invdeg[n];
                *(float4*)&sm.agg[n * HP + (lane << 2)] =
                    make_float4(s.x * iv, s.y * iv, s.z * iv, s.w * iv);
            }
            __syncwarp();
            ull na[5][4]; ZERO5(na);
            gemm5(nw1, c16,
                  sm.h_n + nr[0] * HP, sm.h_n + nr[1] * HP, sm.h_n + nr[2] * HP,
                  sm.h_n + nr[3] * HP, sm.h_n + nr[4] * HP, na, HDIM);
            gemm5(nw1 + HDIM * HDIM, c16,
                  sm.agg + nr[0] * HP, sm.agg + nr[1] * HP, sm.agg + nr[2] * HP,
                  sm.agg + nr[3] * HP, sm.agg + nr[4] * HP, na, HDIM);
            epi5<0>(na, nb1, c16, sm.nhid, HP, nr, nvalid);
        }
        __syncthreads();

        // ===== phase B1: hid = relu(R + P[row] + Q[col] + b1) ==============
        if (wid < 8) {
            float4 b = *(const float4*)(b1 + co);
#pragma unroll
            for (int j = 0; j < 9; ++j) {
                int e = rbase + j;
                float4 P = *(const float4*)&sm.Pm[sm.row_l[e] * HP + co];
                float4 Q = *(const float4*)&sm.Qm[sm.col_l[e] * HP + co];
                float2 p0 = unpack2(acc[j][0]), p1 = unpack2(acc[j][1]);
                *(float4*)&sm.hid[e * EP + co] = make_float4(
                    fmaxf(p0.x + P.x + Q.x + b.x, 0.f),
                    fmaxf(p0.y + P.y + Q.y + b.y, 0.f),
                    fmaxf(p1.x + P.z + Q.z + b.z, 0.f),
                    fmaxf(p1.y + P.w + Q.w + b.w, 0.f));
            }
        }
        __syncthreads();

        // ===== phase B2 =====
        if (wid < 8) {
            // h_e += hid @ W2 + b2
            ull a2[9][2]; ZERO9(a2);
            cgemm72(w2, sm.hid, EP, rbase, co, a2);
            float4 b = *(const float4*)(b2 + co);
#pragma unroll
            for (int j = 0; j < 9; ++j) {
                float* o = &sm.h_e[(rbase + j) * EP + co];
                float4 old = *(const float4*)o;
                float2 p0 = unpack2(a2[j][0]), p1 = unpack2(a2[j][1]);
                *(float4*)o = make_float4(old.x + p0.x + b.x, old.y + p0.y + b.y,
                                          old.z + p1.x + b.z, old.w + p1.y + b.w);
            }
        } else if (wid == 8) {
            // h_n += nhid @ nw2 + nb2
            ull ua[5][4]; ZERO5(ua);
            gemm5(nw2, c16,
                  sm.nhid + nr[0] * HP, sm.nhid + nr[1] * HP, sm.nhid + nr[2] * HP,
                  sm.nhid + nr[3] * HP, sm.nhid + nr[4] * HP, ua, HDIM);
            epi5<1>(ua, nb2, c16, sm.h_n, HP, nr, nvalid);
        }
        __syncthreads();
    }

    // ---- decoder hidden: dhid = relu(h_e @ dec_w1 + dec_b1) ---------------
    float* dhid = sm.hid;
    for (int idx = tid; idx < NEDGE * 16; idx += NTHREADS) {
        int e = idx >> 4, c4 = idx & 15;
        const float* w = dec_w1 + (c4 << 2);
        ull a0 = 0ull, a1 = 0ull;
#pragma unroll 4
        for (int k = 0; k < HDIM; ++k) {
            ull s = pack2(sm.h_e[e * EP + k]);
            ulonglong2 wv = *(const ulonglong2*)(w + k * 64);
            ffma2(a0, s, wv.x); ffma2(a1, s, wv.y);
        }
        float4 b = *(const float4*)(dec_b1 + (c4 << 2));
        float2 p0 = unpack2(a0), p1 = unpack2(a1);
        *(float4*)&dhid[e * DP + (c4 << 2)] =
            make_float4(fmaxf(p0.x + b.x, 0.f), fmaxf(p0.y + b.y, 0.f),
                        fmaxf(p1.x + b.z, 0.f), fmaxf(p1.y + b.w, 0.f));
    }
    __syncthreads();

    // ---- decoder out + sigmoid -------------------------------------------
    if (tid < NEDGE) {
        float a = dec_b2[0];
#pragma unroll 4
        for (int k = 0; k < 64; ++k) a = fmaf(dhid[tid * DP + k], dec_w2[k], a);
        sm.dec[tid] = 1.f / (1.f + expf(-a));
    }
    __syncthreads();
    if (tid < NPAIR)
        out[g * NPAIR + tid] = 0.5f * (sm.dec[2 * tid] + sm.dec[2 * tid + 1]);
}

// ---------------------------------------------------------------------------
// Harness entry point
// ---------------------------------------------------------------------------
extern "C" void kernel_launch(void* const* d_in, const int* in_sizes, int n_in,
                              void* d_out, int out_size)
{
    const float* x_nodes   = (const float*)d_in[0];
    const float* damage    = (const float*)d_in[1];
    const float* enc_n_w   = (const float*)d_in[2];
    const float* enc_n_b   = (const float*)d_in[3];
    const float* enc_e_w1  = (const float*)d_in[4];
    const float* enc_e_b1  = (const float*)d_in[5];
    const float* enc_e_w2  = (const float*)d_in[6];
    const float* enc_e_b2  = (const float*)d_in[7];
    const float* edge_w1   = (const float*)d_in[8];
    const float* edge_b1   = (const float*)d_in[9];
    const float* edge_w2   = (const float*)d_in[10];
    const float* edge_b2   = (const float*)d_in[11];
    const float* node_w1   = (const float*)d_in[12];
    const float* node_b1   = (const float*)d_in[13];
    const float* node_w2   = (const float*)d_in[14];
    const float* node_b2   = (const float*)d_in[15];
    const float* dec_w1    = (const float*)d_in[16];
    const float* dec_b1    = (const float*)d_in[17];
    const float* dec_w2    = (const float*)d_in[18];
    const float* dec_b2    = (const float*)d_in[19];
    const int*   edge_idx  = (const int*)d_in[20];

    int Etot = in_sizes[20] / 2;
    int Bg   = Etot / NEDGE;

    cudaFuncSetAttribute(DirectPathAttenuationGNN_kernel,
                         cudaFuncAttributeMaxDynamicSharedMemorySize,
                         (int)sizeof(SM));

    DirectPathAttenuationGNN_kernel<<<Bg, NTHREADS, sizeof(SM)>>>(
        x_nodes, damage,
        enc_n_w, enc_n_b, enc_e_w1, enc_e_b1, enc_e_w2, enc_e_b2,
        edge_w1, edge_b1, edge_w2, edge_b2,
        node_w1, node_b1, node_w2, node_b2,
        dec_w1, dec_b1, dec_w2, dec_b2,
        edge_idx, Etot,
        (float*)d_out);
}

// round 5
// speedup vs baseline: 1.9085x; 1.0014x over previous
#include <cuda_runtime.h>
#include <math.h>

#define NSENS 9
#define NEDGE 72
#define NPAIR 36
#define HDIM  128
#define NLAY  4
#define NTHREADS 320
#define EPSF 1e-8f
#define EP 132
#define HP 132
#define DP 68

typedef unsigned long long ull;

// Pre-transposed weights: [matrix][col c][k] with k contiguous.
// m=0: enc_e_w2 ; m=1..4: edge_w1 segment-C (layer l) ; m=5..8: edge_w2 (layer l)
__device__ float g_WT[9 * 16384 + 16];

// ---------------------------------------------------------------------------
// Shared memory (one CTA per graph)
// ---------------------------------------------------------------------------
struct SM {
    float h_n[NSENS * HP];
    float agg[NSENS * HP];
    float Pm [NSENS * HP];
    float Qm [NSENS * HP];
    float nhid[NSENS * HP];
    float h_e[NEDGE * EP];
    float hid[NEDGE * EP];
    float phys[NEDGE][8];
    float xs[NSENS][2];
    float dmg[2];
    float invdeg[NSENS];
    float dec[NEDGE];
    int   row_l[NEDGE];
    int   col_l[NEDGE];
    int   senders[NSENS][8];
    int   scnt[NSENS];
};

// ---------------------------------------------------------------------------
// Packed f32x2 helpers
// ---------------------------------------------------------------------------
__device__ __forceinline__ ull pack2(float x) {
    ull r; asm("mov.b64 %0, {%1, %1};" : "=l"(r) : "f"(x)); return r;
}
__device__ __forceinline__ void ffma2(ull& d, ull a, ull b) {
    asm("fma.rn.f32x2 %0, %1, %2, %0;" : "+l"(d) : "l"(a), "l"(b));
}
__device__ __forceinline__ float2 unpack2(ull v) {
    float lo, hi; asm("mov.b64 {%0, %1}, %2;" : "=f"(lo), "=f"(hi) : "l"(v));
    return make_float2(lo, hi);
}

#define ZERO92(A) do {                                                      \
    _Pragma("unroll") for (int _j = 0; _j < 9; ++_j)                        \
    { (A)[_j][0] = 0ull; (A)[_j][1] = 0ull; }                               \
} while (0)

#define ZERO5(A) do {                                                       \
    _Pragma("unroll") for (int _j = 0; _j < 5; ++_j)                        \
    _Pragma("unroll") for (int _p = 0; _p < 4; ++_p) (A)[_j][_p] = 0ull;    \
} while (0)

// ---------------------------------------------------------------------------
// k-paired column pass: thread accumulates 9 rows x 2 cols, f32x2 over (k,k+1).
// A loaded as ulonglong2 (2 k-pairs per LDS.128), WT[c][k] likewise from gmem.
// Per 4k: 2 LDG.128 + 9 LDS.128 + 36 FFMA2 — no pack movs. W prefetched 1 iter ahead.
// ---------------------------------------------------------------------------
__device__ __forceinline__ void kpass(
    const float* __restrict__ WT, const float* __restrict__ A,
    int ast, int rbase, int co, ull (&acc)[9][2])
{
    const float* w0p = WT + co * HDIM;
    const float* w1p = WT + (co + 1) * HDIM;
    ulonglong2 wv0 = *(const ulonglong2*)(w0p);
    ulonglong2 wv1 = *(const ulonglong2*)(w1p);
    const float* ap = A + rbase * ast;
#pragma unroll 1
    for (int kb = 0; kb < HDIM; kb += 4) {
        ulonglong2 nv0 = *(const ulonglong2*)(w0p + kb + 4);  // pad-safe overread
        ulonglong2 nv1 = *(const ulonglong2*)(w1p + kb + 4);
#pragma unroll
        for (int j = 0; j < 9; ++j) {
            ulonglong2 av = *(const ulonglong2*)(ap + j * ast + kb);
            ffma2(acc[j][0], av.x, wv0.x);
            ffma2(acc[j][0], av.y, wv0.y);
            ffma2(acc[j][1], av.x, wv1.x);
            ffma2(acc[j][1], av.y, wv1.y);
        }
        wv0 = nv0; wv1 = nv1;
    }
}

// epilogues: sum the k-parity halves. MODE 0 = raw store, 1 = residual+bias, 2 = bias
template<int MODE>
__device__ __forceinline__ void kepi(
    ull (&acc)[9][2], const float* __restrict__ bias,
    float* __restrict__ O, int ost, int rbase, int co)
{
    float2 b = make_float2(0.f, 0.f);
    if (MODE != 0) b = *(const float2*)(bias + co);
#pragma unroll
    for (int j = 0; j < 9; ++j) {
        float2 p0 = unpack2(acc[j][0]);
        float2 p1 = unpack2(acc[j][1]);
        float s0 = p0.x + p0.y, s1 = p1.x + p1.y;
        float* o = O + (rbase + j) * ost + co;
        if (MODE == 0) {
            *(float2*)o = make_float2(s0, s1);
        } else if (MODE == 1) {
            float2 old = *(const float2*)o;
            *(float2*)o = make_float2(old.x + s0 + b.x, old.y + s1 + b.y);
        } else {
            *(float2*)o = make_float2(s0 + b.x, s1 + b.y);
        }
    }
}

// two-pass wrapper covering this warp's 16 columns
template<int MODE>
__device__ __forceinline__ void kgemm72(
    const float* __restrict__ WT, const float* __restrict__ A, int ast,
    const float* __restrict__ bias, float* __restrict__ O, int ost,
    int rbase, int cobase)
{
#pragma unroll 1
    for (int p = 0; p < 2; ++p) {
        ull acc[9][2]; ZERO92(acc);
        int co = cobase + p * 8;
        kpass(WT, A, ast, rbase, co, acc);
        kepi<MODE>(acc, bias, O, ost, rbase, co);
    }
}

// ---------------------------------------------------------------------------
// Row-tiled 5-row GEMM for node-side warps (row-major fp32 W), as in R4
// ---------------------------------------------------------------------------
#define STEP5(AX, W0, W1) do {                                              \
    ull s0 = pack2(v0.AX), s1 = pack2(v1.AX), s2 = pack2(v2.AX);            \
    ull s3 = pack2(v3.AX), s4 = pack2(v4.AX);                               \
    ffma2(acc[0][0], s0, (W0).x); ffma2(acc[0][1], s0, (W0).y);             \
    ffma2(acc[0][2], s0, (W1).x); ffma2(acc[0][3], s0, (W1).y);             \
    ffma2(acc[1][0], s1, (W0).x); ffma2(acc[1][1], s1, (W0).y);             \
    ffma2(acc[1][2], s1, (W1).x); ffma2(acc[1][3], s1, (W1).y);             \
    ffma2(acc[2][0], s2, (W0).x); ffma2(acc[2][1], s2, (W0).y);             \
    ffma2(acc[2][2], s2, (W1).x); ffma2(acc[2][3], s2, (W1).y);             \
    ffma2(acc[3][0], s3, (W0).x); ffma2(acc[3][1], s3, (W0).y);             \
    ffma2(acc[3][2], s3, (W1).x); ffma2(acc[3][3], s3, (W1).y);             \
    ffma2(acc[4][0], s4, (W0).x); ffma2(acc[4][1], s4, (W0).y);             \
    ffma2(acc[4][2], s4, (W1).x); ffma2(acc[4][3], s4, (W1).y);             \
} while (0)

__device__ __forceinline__ void gemm5(
    const float* __restrict__ W, int c16,
    const float* __restrict__ a0, const float* __restrict__ a1,
    const float* __restrict__ a2, const float* __restrict__ a3,
    const float* __restrict__ a4,
    ull (&acc)[5][4], int K)
{
    const float* wp = W + (c16 << 3);
#pragma unroll 1
    for (int kb = 0; kb < K; kb += 4) {
        float4 v0 = *(const float4*)(a0 + kb);
        float4 v1 = *(const float4*)(a1 + kb);
        float4 v2 = *(const float4*)(a2 + kb);
        float4 v3 = *(const float4*)(a3 + kb);
        float4 v4 = *(const float4*)(a4 + kb);
        const float* wk = wp + kb * HDIM;
        ulonglong2 wA0 = *(const ulonglong2*)(wk);
        ulonglong2 wA1 = *(const ulonglong2*)(wk + 4);
        ulonglong2 wB0 = *(const ulonglong2*)(wk + HDIM);
        ulonglong2 wB1 = *(const ulonglong2*)(wk + HDIM + 4);
        STEP5(x, wA0, wA1);
        wA0 = *(const ulonglong2*)(wk + 2 * HDIM);
        wA1 = *(const ulonglong2*)(wk + 2 * HDIM + 4);
        STEP5(y, wB0, wB1);
        wB0 = *(const ulonglong2*)(wk + 3 * HDIM);
        wB1 = *(const ulonglong2*)(wk + 3 * HDIM + 4);
        STEP5(z, wA0, wA1);
        STEP5(w, wB0, wB1);
    }
}

// MODE: 0 = relu(acc+bias), 1 = out += acc+bias, 3 = raw
template<int MODE>
__device__ __forceinline__ void epi5(
    ull (&acc)[5][4], const float* __restrict__ bias, int c16,
    float* __restrict__ outBase, int ostride, const int* r, int nvalid)
{
    const int co = c16 << 3;
    float4 b0 = make_float4(0.f, 0.f, 0.f, 0.f), b1 = b0;
    if (MODE != 3) {
        b0 = *(const float4*)(bias + co);
        b1 = *(const float4*)(bias + co + 4);
    }
#pragma unroll
    for (int j = 0; j < 5; ++j) {
        if (j >= nvalid) break;
        float2 p0 = unpack2(acc[j][0]), p1 = unpack2(acc[j][1]);
        float2 p2 = unpack2(acc[j][2]), p3 = unpack2(acc[j][3]);
        float lo0 = p0.x + b0.x, lo1 = p0.y + b0.y, lo2 = p1.x + b0.z, lo3 = p1.y + b0.w;
        float hi0 = p2.x + b1.x, hi1 = p2.y + b1.y, hi2 = p3.x + b1.z, hi3 = p3.y + b1.w;
        float* o = outBase + r[j] * ostride + co;
        if (MODE == 0) {
            *(float4*)o       = make_float4(fmaxf(lo0,0.f), fmaxf(lo1,0.f), fmaxf(lo2,0.f), fmaxf(lo3,0.f));
            *(float4*)(o + 4) = make_float4(fmaxf(hi0,0.f), fmaxf(hi1,0.f), fmaxf(hi2,0.f), fmaxf(hi3,0.f));
        } else if (MODE == 1) {
            float4 x0 = *(const float4*)o, x1 = *(const float4*)(o + 4);
            *(float4*)o       = make_float4(x0.x + lo0, x0.y + lo1, x0.z + lo2, x0.w + lo3);
            *(float4*)(o + 4) = make_float4(x1.x + hi0, x1.y + hi1, x1.z + hi2, x1.w + hi3);
        } else {
            *(float4*)o       = make_float4(lo0, lo1, lo2, lo3);
            *(float4*)(o + 4) = make_float4(hi0, hi1, hi2, hi3);
        }
    }
}

// ---------------------------------------------------------------------------
// Prep kernel: transpose the 128-col weight matrices into g_WT[(m*128+c)*128+k]
// ---------------------------------------------------------------------------
__global__ void prep_wt_kernel(const float* __restrict__ enc_e_w2,
                               const float* __restrict__ edge_w1,
                               const float* __restrict__ edge_w2)
{
    int i = blockIdx.x * blockDim.x + threadIdx.x;
    if (i >= 9 * 16384) return;
    int m = i >> 14;
    int r = i & 16383;
    int c = r >> 7;
    int k = r & 127;
    float v;
    if (m == 0)      v = enc_e_w2[k * HDIM + c];
    else if (m <= 4) v = edge_w1[(m - 1) * 3 * HDIM * HDIM + (2 * HDIM + k) * HDIM + c];
    else             v = edge_w2[(m - 5) * HDIM * HDIM + k * HDIM + c];
    g_WT[i] = v;
}

// ---------------------------------------------------------------------------
// Fused GNN kernel: one CTA per graph, 320 threads (10 warps)
// ---------------------------------------------------------------------------
__global__ __launch_bounds__(NTHREADS, 2)
void DirectPathAttenuationGNN_kernel(
    const float* __restrict__ x_nodes, const float* __restrict__ damage,
    const float* __restrict__ enc_n_w, const float* __restrict__ enc_n_b,
    const float* __restrict__ enc_e_w1, const float* __restrict__ enc_e_b1,
    const float* __restrict__ enc_e_b2,
    const float* __restrict__ edge_w1, const float* __restrict__ edge_b1,
    const float* __restrict__ edge_b2,
    const float* __restrict__ node_w1, const float* __restrict__ node_b1,
    const float* __restrict__ node_w2, const float* __restrict__ node_b2,
    const float* __restrict__ dec_w1, const float* __restrict__ dec_b1,
    const float* __restrict__ dec_w2, const float* __restrict__ dec_b2,
    const int* __restrict__ edge_index, int Etot,
    float* __restrict__ out)
{
    extern __shared__ unsigned char smem_raw[];
    SM& sm = *reinterpret_cast<SM*>(smem_raw);

    const int g    = blockIdx.x;
    const int tid  = threadIdx.x;
    const int wid  = tid >> 5;
    const int lane = tid & 31;

    // k-paired column tiling for edge warps 0-7
    const int rbase  = (lane >> 2) * 9;            // 9 rows
    const int cobase = wid * 16 + (lane & 3) * 2;  // 2 cols per pass, 2 passes (+8)

    // row-tiled layout for node warps 8-9
    const int hw  = lane >> 4;
    const int c16 = lane & 15;
    int nr[5]; int nvalid = hw ? 4 : 5;
    {
        int base = hw * 5;
#pragma unroll
        for (int j = 0; j < 5; ++j) { int r = base + j; nr[j] = r < 8 ? r : 8; }
    }

    // ---- per-graph inputs -------------------------------------------------
    if (tid < NEDGE) {
        int ge = g * NEDGE + tid;
        sm.row_l[tid] = edge_index[ge]        - g * NSENS;
        sm.col_l[tid] = edge_index[Etot + ge] - g * NSENS;
    }
    if (tid < NSENS * 2) ((float*)sm.xs)[tid] = x_nodes[g * NSENS * 2 + tid];
    if (tid < 2)         sm.dmg[tid] = damage[g * 2 + tid];
    __syncthreads();

    // ---- sender lists + degree -------------------------------------------
    if (tid < NSENS) {
        int cnt = 0;
        for (int e = 0; e < NEDGE; ++e)
            if (sm.col_l[e] == tid) { if (cnt < 8) sm.senders[tid][cnt] = sm.row_l[e]; ++cnt; }
        sm.scnt[tid]   = cnt < 8 ? cnt : 8;
        sm.invdeg[tid] = 1.0f / fmaxf((float)cnt, 1.0f);
    }

    // ---- physical edge features ------------------------------------------
    if (tid < NEDGE) {
        int r = sm.row_l[tid], c = sm.col_l[tid];
        float sx = sm.xs[r][0], sy = sm.xs[r][1];
        float dx = sm.xs[c][0], dy = sm.xs[c][1];
        float g0 = sm.dmg[0],   g1 = sm.dmg[1];
        float vx = sx - dx, vy = sy - dy;
        float elen = sqrtf(vx * vx + vy * vy + EPSF);
        float d21x = -vx, d21y = -vy;
        float l2 = fmaxf(d21x * d21x + d21y * d21y, EPSF);
        float mx = g0 - sx, my = g1 - sy;
        float t = fminf(fmaxf((mx * d21x + my * d21y) / l2, 0.f), 1.f);
        float px = sx + t * d21x, py = sy + t * d21y;
        float qx = g0 - px, qy = g1 - py;
        float d_path = sqrtf(qx * qx + qy * qy + EPSF);
        float d_tx = sqrtf(mx * mx + my * my + EPSF);
        float rx = dx - g0, ry = dy - g1;
        float d_rx = sqrtf(rx * rx + ry * ry + EPSF);
        sm.phys[tid][0] = vx;   sm.phys[tid][1] = vy;
        sm.phys[tid][2] = elen; sm.phys[tid][3] = d_path;
        sm.phys[tid][4] = d_tx; sm.phys[tid][5] = d_rx;
    }

    // ---- node encoder (K=2) ----------------------------------------------
    if (tid < NSENS * 32) {
        int n = tid >> 5, c4 = lane;
        float x0 = sm.xs[n][0], x1 = sm.xs[n][1];
        float4 w0 = *(const float4*)(enc_n_w + (c4 << 2));
        float4 w1 = *(const float4*)(enc_n_w + HDIM + (c4 << 2));
        float4 b  = *(const float4*)(enc_n_b + (c4 << 2));
        *(float4*)&sm.h_n[n * HP + (c4 << 2)] =
            make_float4(fmaf(x1, w1.x, fmaf(x0, w0.x, b.x)),
                        fmaf(x1, w1.y, fmaf(x0, w0.y, b.y)),
                        fmaf(x1, w1.z, fmaf(x0, w0.z, b.z)),
                        fmaf(x1, w1.w, fmaf(x0, w0.w, b.w)));
    }
    __syncthreads();

    // ---- edge encoder hidden (K=6) -> hid ---------------------------------
    for (int idx = tid; idx < NEDGE * 32; idx += NTHREADS) {
        int e = idx >> 5, c4 = idx & 31;
        float4 a = *(const float4*)(enc_e_b1 + (c4 << 2));
#pragma unroll
        for (int k = 0; k < 6; ++k) {
            float p = sm.phys[e][k];
            float4 wv = *(const float4*)(enc_e_w1 + k * HDIM + (c4 << 2));
            a.x = fmaf(p, wv.x, a.x); a.y = fmaf(p, wv.y, a.y);
            a.z = fmaf(p, wv.z, a.z); a.w = fmaf(p, wv.w, a.w);
        }
        *(float4*)&sm.hid[e * EP + (c4 << 2)] =
            make_float4(fmaxf(a.x, 0.f), fmaxf(a.y, 0.f), fmaxf(a.z, 0.f), fmaxf(a.w, 0.f));
    }
    __syncthreads();

    // ---- edge encoder out: h_e = hid @ W2 + b2 ----------------------------
    if (wid < 8)
        kgemm72<2>(g_WT, sm.hid, EP, enc_e_b2, sm.h_e, EP, rbase, cobase);
    __syncthreads();

    // ---- 4 message-passing layers -----------------------------------------
    for (int l = 0; l < NLAY; ++l) {
        const float* w1   = edge_w1 + l * 3 * HDIM * HDIM;
        const float* b1   = edge_b1 + l * HDIM;
        const float* b2   = edge_b2 + l * HDIM;
        const float* wt1c = g_WT + (1 + l) * 16384;
        const float* wt2  = g_WT + (5 + l) * 16384;
        const float* nw1  = node_w1 + l * 2 * HDIM * HDIM;
        const float* nb1  = node_b1 + l * HDIM;
        const float* nw2  = node_w2 + l * HDIM * HDIM;
        const float* nb2  = node_b2 + l * HDIM;

        // ===== phase A =====
        if (wid < 8) {
            // hid = h_e @ W1c   (raw)
            kgemm72<0>(wt1c, sm.h_e, EP, nullptr, sm.hid, EP, rbase, cobase);
        } else if (wid == 8) {
            // P = h_n @ W1a ; Q = h_n @ W1b
            ull pa[5][4]; ZERO5(pa);
            gemm5(w1, c16,
                  sm.h_n + nr[0] * HP, sm.h_n + nr[1] * HP, sm.h_n + nr[2] * HP,
                  sm.h_n + nr[3] * HP, sm.h_n + nr[4] * HP, pa, HDIM);
            epi5<3>(pa, nullptr, c16, sm.Pm, HP, nr, nvalid);
            ZERO5(pa);
            gemm5(w1 + HDIM * HDIM, c16,
                  sm.h_n + nr[0] * HP, sm.h_n + nr[1] * HP, sm.h_n + nr[2] * HP,
                  sm.h_n + nr[3] * HP, sm.h_n + nr[4] * HP, pa, HDIM);
            epi5<3>(pa, nullptr, c16, sm.Qm, HP, nr, nvalid);
        } else { // wid == 9: agg then node hidden
            for (int n = 0; n < NSENS; ++n) {
                float4 s = make_float4(0.f, 0.f, 0.f, 0.f);
                int c = sm.scnt[n];
                for (int i = 0; i < c; ++i) {
                    float4 v = *(const float4*)&sm.h_n[sm.senders[n][i] * HP + (lane << 2)];
                    s.x += v.x; s.y += v.y; s.z += v.z; s.w += v.w;
                }
                float iv = sm.invdeg[n];
                *(float4*)&sm.agg[n * HP + (lane << 2)] =
                    make_float4(s.x * iv, s.y * iv, s.z * iv, s.w * iv);
            }
            __syncwarp();
            ull na[5][4]; ZERO5(na);
            gemm5(nw1, c16,
                  sm.h_n + nr[0] * HP, sm.h_n + nr[1] * HP, sm.h_n + nr[2] * HP,
                  sm.h_n + nr[3] * HP, sm.h_n + nr[4] * HP, na, HDIM);
            gemm5(nw1 + HDIM * HDIM, c16,
                  sm.agg + nr[0] * HP, sm.agg + nr[1] * HP, sm.agg + nr[2] * HP,
                  sm.agg + nr[3] * HP, sm.agg + nr[4] * HP, na, HDIM);
            epi5<0>(na, nb1, c16, sm.nhid, HP, nr, nvalid);
        }
        __syncthreads();

        // ===== phase B1 (all warps): hid = relu(hid + P[row] + Q[col] + b1) =
        for (int idx = tid; idx < NEDGE * 32; idx += NTHREADS) {
            int e = idx >> 5, c4 = idx & 31;
            int coff = c4 << 2;
            float4 r = *(const float4*)&sm.hid[e * EP + coff];
            float4 P = *(const float4*)&sm.Pm[sm.row_l[e] * HP + coff];
            float4 Q = *(const float4*)&sm.Qm[sm.col_l[e] * HP + coff];
            float4 b = *(const float4*)(b1 + coff);
            *(float4*)&sm.hid[e * EP + coff] = make_float4(
                fmaxf(r.x + P.x + Q.x + b.x, 0.f),
                fmaxf(r.y + P.y + Q.y + b.y, 0.f),
                fmaxf(r.z + P.z + Q.z + b.z, 0.f),
                fmaxf(r.w + P.w + Q.w + b.w, 0.f));
        }
        __syncthreads();

        // ===== phase B2 =====
        if (wid < 8) {
            // h_e += hid @ W2 + b2
            kgemm72<1>(wt2, sm.hid, EP, b2, sm.h_e, EP, rbase, cobase);
        } else if (wid == 8) {
            // h_n += nhid @ nw2 + nb2
            ull ua[5][4]; ZERO5(ua);
            gemm5(nw2, c16,
                  sm.nhid + nr[0] * HP, sm.nhid + nr[1] * HP, sm.nhid + nr[2] * HP,
                  sm.nhid + nr[3] * HP, sm.nhid + nr[4] * HP, ua, HDIM);
            epi5<1>(ua, nb2, c16, sm.h_n, HP, nr, nvalid);
        }
        __syncthreads();
    }

    // ---- decoder hidden: dhid = relu(h_e @ dec_w1 + dec_b1) ---------------
    float* dhid = sm.hid;
    for (int idx = tid; idx < NEDGE * 16; idx += NTHREADS) {
        int e = idx >> 4, c4 = idx & 15;
        const float* w = dec_w1 + (c4 << 2);
        ull a0 = 0ull, a1 = 0ull;
#pragma unroll 4
        for (int k = 0; k < HDIM; ++k) {
            ull s = pack2(sm.h_e[e * EP + k]);
            ulonglong2 wv = *(const ulonglong2*)(w + k * 64);
            ffma2(a0, s, wv.x); ffma2(a1, s, wv.y);
        }
        float4 b = *(const float4*)(dec_b1 + (c4 << 2));
        float2 p0 = unpack2(a0), p1 = unpack2(a1);
        *(float4*)&dhid[e * DP + (c4 << 2)] =
            make_float4(fmaxf(p0.x + b.x, 0.f), fmaxf(p0.y + b.y, 0.f),
                        fmaxf(p1.x + b.z, 0.f), fmaxf(p1.y + b.w, 0.f));
    }
    __syncthreads();

    // ---- decoder out + sigmoid -------------------------------------------
    if (tid < NEDGE) {
        float a = dec_b2[0];
#pragma unroll 4
        for (int k = 0; k < 64; ++k) a = fmaf(dhid[tid * DP + k], dec_w2[k], a);
        sm.dec[tid] = 1.f / (1.f + expf(-a));
    }
    __syncthreads();
    if (tid < NPAIR)
        out[g * NPAIR + tid] = 0.5f * (sm.dec[2 * tid] + sm.dec[2 * tid + 1]);
}

// ---------------------------------------------------------------------------
// Harness entry point: prep (weight transpose) then fused kernel
// ---------------------------------------------------------------------------
extern "C" void kernel_launch(void* const* d_in, const int* in_sizes, int n_in,
                              void* d_out, int out_size)
{
    const float* x_nodes   = (const float*)d_in[0];
    const float* damage    = (const float*)d_in[1];
    const float* enc_n_w   = (const float*)d_in[2];
    const float* enc_n_b   = (const float*)d_in[3];
    const float* enc_e_w1  = (const float*)d_in[4];
    const float* enc_e_b1  = (const float*)d_in[5];
    const float* enc_e_w2  = (const float*)d_in[6];
    const float* enc_e_b2  = (const float*)d_in[7];
    const float* edge_w1   = (const float*)d_in[8];
    const float* edge_b1   = (const float*)d_in[9];
    const float* edge_w2   = (const float*)d_in[10];
    const float* edge_b2   = (const float*)d_in[11];
    const float* node_w1   = (const float*)d_in[12];
    const float* node_b1   = (const float*)d_in[13];
    const float* node_w2   = (const float*)d_in[14];
    const float* node_b2   = (const float*)d_in[15];
    const float* dec_w1    = (const float*)d_in[16];
    const float* dec_b1    = (const float*)d_in[17];
    const float* dec_w2    = (const float*)d_in[18];
    const float* dec_b2    = (const float*)d_in[19];
    const int*   edge_idx  = (const int*)d_in[20];

    int Etot = in_sizes[20] / 2;
    int Bg   = Etot / NEDGE;

    prep_wt_kernel<<<(9 * 16384 + 255) / 256, 256>>>(enc_e_w2, edge_w1, edge_w2);

    cudaFuncSetAttribute(DirectPathAttenuationGNN_kernel,
                         cudaFuncAttributeMaxDynamicSharedMemorySize,
                         (int)sizeof(SM));

    DirectPathAttenuationGNN_kernel<<<Bg, NTHREADS, sizeof(SM)>>>(
        x_nodes, damage,
        enc_n_w, enc_n_b, enc_e_w1, enc_e_b1, enc_e_b2,
        edge_w1, edge_b1, edge_b2,
        node_w1, node_b1, node_w2, node_b2,
        dec_w1, dec_b1, dec_w2, dec_b2,
        edge_idx, Etot,
        (float*)d_out);
}